// round 4
// baseline (speedup 1.0000x reference)
#include <cuda_runtime.h>

#define DINLINE __device__ __forceinline__

constexpr int N   = 50000;
constexpr int E   = 800000;
constexpr int F   = 128;
constexpr int DIM = 128;
constexpr int NF  = 4;
constexpr int ND  = 32;
constexpr int NL  = 3;
constexpr int NC  = 10;
constexpr int G   = 256;

constexpr int OFF_PRED = 0;
constexpr int OFF_ATT  = G * NC;            // 2560
constexpr int OFF_OUTS = OFF_ATT + NF * E;  // 3202560

typedef unsigned long long u64;

// ------------------------- scratch (device globals, no cudaMalloc) ---------
__device__ float  g_state[N * DIM];
__device__ float  g_agg[N * DIM];
__device__ float  g_el[N * NF];
__device__ float  g_er[N * NF];
__device__ float  g_vl[NF * F];
__device__ float  g_vr[NF * F];
__device__ float  g_elb[NF];
__device__ float  g_erb[NF];
__device__ int    g_cnt[N];
__device__ int    g_rowptr[N + 1];
__device__ int    g_fill[N];
__device__ int    g_csr_src[E];
__device__ float4 g_att_t[E];
__device__ float4 g_csr_att[E];
__device__ float  g_pooled[G * DIM];

DINLINE float sigm(float x)   { return __fdividef(1.f, 1.f + __expf(-x)); }
DINLINE float tanh_f(float x) { return 1.f - __fdividef(2.f, __expf(2.f * x) + 1.f); }

// ---- packed f32x2 helpers (FFMA2 — only reachable via PTX) ----------------
DINLINE u64 splat2(float x) { u64 r; asm("mov.b64 %0, {%1, %1};" : "=l"(r) : "f"(x)); return r; }
DINLINE float2 unpack2(u64 v) {
    float lo, hi;
    asm("mov.b64 {%0, %1}, %2;" : "=f"(lo), "=f"(hi) : "l"(v));
    return make_float2(lo, hi);
}
DINLINE u64 ffma2(u64 a, u64 b, u64 c) {
    u64 d;
    asm("fma.rn.f32x2 %0, %1, %2, %3;" : "=l"(d) : "l"(a), "l"(b), "l"(c));
    return d;
}

// ------------------------- K1: fold lin0/att into per-node vectors ---------
__global__ void k_pre(const float* __restrict__ lin0_W, const float* __restrict__ lin0_b,
                      const float* __restrict__ att_W,  const float* __restrict__ att_b) {
    int f = blockIdx.x;
    int k = threadIdx.x;
    const float* W  = lin0_W + (f * F + k) * DIM;
    const float* wl = att_W + f * 2 * DIM;
    const float* wr = wl + DIM;
    float sl = 0.f, sr = 0.f;
    for (int d = 0; d < DIM; d++) { float w = W[d]; sl = fmaf(w, wl[d], sl); sr = fmaf(w, wr[d], sr); }
    g_vl[f * F + k] = sl;
    g_vr[f * F + k] = sr;
    if (k == 0) {
        float bl = att_b[f], br = 0.f;
        const float* b0 = lin0_b + f * DIM;
        for (int d = 0; d < DIM; d++) { bl = fmaf(b0[d], wl[d], bl); br = fmaf(b0[d], wr[d], br); }
        g_elb[f] = bl;
        g_erb[f] = br;
    }
}

// ------------------------- K2: node init (enc GEMM + el/er GEMVs) ----------
constexpr int NPB = 16;  // nodes per block
__global__ __launch_bounds__(128) void k_init(const float* __restrict__ x,
                                              const float* __restrict__ enc_W,
                                              const float* __restrict__ enc_b) {
    extern __shared__ float sm[];
    float* ws = sm;                   // [k][c] : 128*128
    float* wv = ws + NF * F * ND;     // vl(512) then vr(512)
    float* xs = wv + 2 * NF * F;      // [k][NPB] : 128*16

    int tid = threadIdx.x;
    for (int i = tid; i < NF * F * ND; i += 128) {
        int c = i & 127, k = i >> 7;
        int f = c >> 5, d = c & 31;
        ws[i] = enc_W[(f * F + k) * ND + d];
    }
    for (int i = tid; i < 2 * NF * F; i += 128)
        wv[i] = (i < NF * F) ? g_vl[i] : g_vr[i - NF * F];

    int n0 = blockIdx.x * NPB;
    for (int n = 0; n < NPB; n++) {
        int node = n0 + n;
        xs[tid * NPB + n] = (node < N) ? x[node * F + tid] : 0.f;
    }
    __syncthreads();

    int c = tid;
    u64 acc2[NPB / 2];
#pragma unroll
    for (int q = 0; q < NPB / 2; q++) acc2[q] = 0ull;
    for (int k = 0; k < F; k++) {
        u64 w2 = splat2(ws[k * 128 + c]);
        const ulonglong2* xv = (const ulonglong2*)&xs[k * NPB];
#pragma unroll
        for (int q = 0; q < NPB / 4; q++) {
            ulonglong2 v = xv[q];
            acc2[q * 2 + 0] = ffma2(v.x, w2, acc2[q * 2 + 0]);
            acc2[q * 2 + 1] = ffma2(v.y, w2, acc2[q * 2 + 1]);
        }
    }
    int f = c >> 5, d = c & 31;
    float b = enc_b[f * ND + d];
#pragma unroll
    for (int q = 0; q < NPB / 2; q++) {
        float2 v = unpack2(acc2[q]);
        int na = n0 + 2 * q, nb = na + 1;
        if (na < N) g_state[na * DIM + c] = v.x + b;
        if (nb < N) g_state[nb * DIM + c] = v.y + b;
    }

    // el/er: 128 threads = 16 nodes x 8 (4 factors x {l,r})
    int nn  = tid >> 3;
    int idx = tid & 7;
    int ff  = idx & 3;
    int isR = idx >> 2;
    const float* vec = &wv[isR * NF * F + ff * F];
    float a = 0.f;
    for (int k = 0; k < F; k++) a = fmaf(xs[k * NPB + nn], vec[k], a);
    int node = n0 + nn;
    if (node < N) {
        if (isR) g_er[node * NF + ff] = a + g_erb[ff];
        else     g_el[node * NF + ff] = a + g_elb[ff];
    }
}

// ------------------------- K3: per-edge attention (+ zero cnt fused) -------
__global__ void k_att(const int* __restrict__ ei, float* __restrict__ out_att) {
    int e = blockIdx.x * blockDim.x + threadIdx.x;
    if (e < N) g_cnt[e] = 0;
    if (e >= E) return;
    int s = ei[e], d = ei[E + e];
    float4 el = *(const float4*)&g_el[s * 4];
    float4 er = *(const float4*)&g_er[d * 4];
    float4 a;
    a.x = sigm(6.f * (el.x + er.x));
    a.y = sigm(6.f * (el.y + er.y));
    a.z = sigm(6.f * (el.z + er.z));
    a.w = sigm(6.f * (el.w + er.w));
    out_att[0 * E + e] = a.x;
    out_att[1 * E + e] = a.y;
    out_att[2 * E + e] = a.z;
    out_att[3 * E + e] = a.w;
    g_att_t[e] = a;
}

// ------------------------- K4: CSR build -----------------------------------
__global__ void k_hist(const int* __restrict__ ei) {
    int e = blockIdx.x * blockDim.x + threadIdx.x;
    if (e < E) atomicAdd(&g_cnt[ei[E + e]], 1);
}
__global__ __launch_bounds__(1024) void k_scan() {
    __shared__ int ssum[1024];
    int t = threadIdx.x;
    const int CH = (N + 1023) / 1024;  // 49
    int base = t * CH;
    int s = 0;
    for (int i = 0; i < CH; i++) { int idx = base + i; if (idx < N) s += g_cnt[idx]; }
    ssum[t] = s;
    __syncthreads();
    for (int off = 1; off < 1024; off <<= 1) {
        int v = (t >= off) ? ssum[t - off] : 0;
        __syncthreads();
        ssum[t] += v;
        __syncthreads();
    }
    int run = ssum[t] - s;  // exclusive
    for (int i = 0; i < CH; i++) {
        int idx = base + i;
        if (idx < N) {
            g_rowptr[idx] = run;
            g_fill[idx]   = run;
            run += g_cnt[idx];
        }
    }
    if (t == 1023) g_rowptr[N] = ssum[1023];
}
__global__ void k_scatter(const int* __restrict__ ei) {
    int e = blockIdx.x * blockDim.x + threadIdx.x;
    if (e >= E) return;
    int s = ei[e], d = ei[E + e];
    int pos = atomicAdd(&g_fill[d], 1);
    g_csr_src[pos] = s;
    g_csr_att[pos] = g_att_t[e];
}

// ------------------------- K5: per-layer aggregation (warp per node) -------
__global__ __launch_bounds__(256) void k_agg() {
    int warp = (blockIdx.x * blockDim.x + threadIdx.x) >> 5;
    int lane = threadIdx.x & 31;
    if (warp >= N) return;
    int beg = g_rowptr[warp], end = g_rowptr[warp + 1];
    const float4* sp = (const float4*)g_state;
    int f = lane >> 3;
    float ax = 0.f, ay = 0.f, az = 0.f, aw = 0.f;
    for (int p = beg; p < end; p++) {
        int src  = __ldg(&g_csr_src[p]);
        float4 at = g_csr_att[p];
        float av = (f == 0) ? at.x : (f == 1) ? at.y : (f == 2) ? at.z : at.w;
        float4 v = sp[src * 32 + lane];
        ax = fmaf(av, v.x, ax);
        ay = fmaf(av, v.y, ay);
        az = fmaf(av, v.z, az);
        aw = fmaf(av, v.w, aw);
    }
    ((float4*)g_agg)[warp * 32 + lane] = make_float4(ax, ay, az, aw);
}

// ------------------------- K6: fused conv + GRU update (f32x2 packed) ------
// Block: 256 threads = 8 warps. Each block: 64 nodes x 1 factor.
// Warp w handles nodes n0+8w .. n0+8w+7; lane d owns output dim d.
// GRU algebra: r,z gates need only (gi+gh) sums -> single accumulator each;
// n gate keeps inn (bih + m@Wih_n) and hn (bhh + h@Whh_n) separate.
constexpr int UPD_NPB   = 64;
constexpr int AO_PITCH  = 72;   // 32 rows of 64 nodes, padded, 16B-aligned rows
constexpr int MS_PITCH  = 10;   // per-warp m staging [d][8], padded vs bank conflicts
__global__ __launch_bounds__(256) void k_update(
    const float* __restrict__ Wrel, const float* __restrict__ brel,
    const float* __restrict__ Wroot,
    const float* __restrict__ Wih, const float* __restrict__ Whh,
    const float* __restrict__ bih, const float* __restrict__ bhh, int l) {
    extern __shared__ float sm[];
    float* sWrel  = sm;                 // [j][d]   1024
    float* sWroot = sWrel + 1024;       // [j][d]   1024
    float* sWih   = sWroot + 1024;      // [g][j][d] 3072
    float* sWhh   = sWih + 3072;        // [g][j][d] 3072
    float* sb_rz  = sWhh + 3072;        // bih+bhh for gates r,z: 64
    float* sb_in  = sb_rz + 64;         // bih n-gate: 32
    float* sb_hn  = sb_in + 32;         // bhh n-gate: 32
    float* sbrel  = sb_hn + 32;         // 32
    float* as_    = sbrel + 32;         // [j][64] pitch 72 : 2304
    float* os_    = as_ + 32 * AO_PITCH;// 2304
    float* ms_    = os_ + 32 * AO_PITCH;// 8 warps * 32*MS_PITCH = 2560

    int f   = blockIdx.y;
    int tid = threadIdx.x;

    const float* Wrel_g  = Wrel + (f * NL + l) * ND * ND;
    const float* Wroot_g = Wroot + (f * NL + l) * ND * ND;
    for (int i = tid; i < ND * ND; i += 256) { sWrel[i] = Wrel_g[i]; sWroot[i] = Wroot_g[i]; }
    const float* Wih_g = Wih + f * 3 * ND * ND;
    const float* Whh_g = Whh + f * 3 * ND * ND;
    for (int i = tid; i < 3 * ND * ND; i += 256) {
        int g = i >> 10, r = (i >> 5) & 31, j = i & 31;  // global = [(g*32+r)][j]
        sWih[(g * 32 + j) * 32 + r] = Wih_g[i];
        sWhh[(g * 32 + j) * 32 + r] = Whh_g[i];
    }
    if (tid < 64) sb_rz[tid] = bih[f * 96 + tid] + bhh[f * 96 + tid];
    if (tid < 32) {
        sb_in[tid] = bih[f * 96 + 64 + tid];
        sb_hn[tid] = bhh[f * 96 + 64 + tid];
        sbrel[tid] = brel[(f * NL + l) * ND + tid];
    }

    int n0 = blockIdx.x * UPD_NPB;
    for (int u = tid; u < 32 * UPD_NPB; u += 256) {
        int j = u & 31, n = u >> 5, node = n0 + n;
        float a = 0.f, o = 0.f;
        if (node < N) {
            a = g_agg[node * DIM + f * ND + j];
            o = g_state[node * DIM + f * ND + j];
        }
        as_[j * AO_PITCH + n] = a;
        os_[j * AO_PITCH + n] = o;
    }
    __syncthreads();

    int w = tid >> 5, d = tid & 31, nl = w * 8;

    u64 m[4], sr[4], sz[4], hn[4];
    {
        u64 bm = splat2(sbrel[d]);
        u64 br = splat2(sb_rz[d]);
        u64 bz = splat2(sb_rz[32 + d]);
        u64 bn = splat2(sb_hn[d]);
#pragma unroll
        for (int q = 0; q < 4; q++) { m[q] = bm; sr[q] = br; sz[q] = bz; hn[q] = bn; }
    }

    // Loop A: m = agg@Wrel + out@Wroot (+relu later); sr/sz/hn += out@Whh
#pragma unroll 4
    for (int j = 0; j < 32; j++) {
        const ulonglong2* ap = (const ulonglong2*)(as_ + j * AO_PITCH + nl);
        const ulonglong2* op = (const ulonglong2*)(os_ + j * AO_PITCH + nl);
        ulonglong2 aA = ap[0], aB = ap[1];
        ulonglong2 oA = op[0], oB = op[1];
        u64 wr2 = splat2(sWrel[j * 32 + d]);
        u64 wo2 = splat2(sWroot[j * 32 + d]);
        u64 hr2 = splat2(sWhh[(0 * 32 + j) * 32 + d]);
        u64 hz2 = splat2(sWhh[(1 * 32 + j) * 32 + d]);
        u64 hn2 = splat2(sWhh[(2 * 32 + j) * 32 + d]);
        m[0] = ffma2(aA.x, wr2, m[0]); m[1] = ffma2(aA.y, wr2, m[1]);
        m[2] = ffma2(aB.x, wr2, m[2]); m[3] = ffma2(aB.y, wr2, m[3]);
        m[0] = ffma2(oA.x, wo2, m[0]); m[1] = ffma2(oA.y, wo2, m[1]);
        m[2] = ffma2(oB.x, wo2, m[2]); m[3] = ffma2(oB.y, wo2, m[3]);
        sr[0] = ffma2(oA.x, hr2, sr[0]); sr[1] = ffma2(oA.y, hr2, sr[1]);
        sr[2] = ffma2(oB.x, hr2, sr[2]); sr[3] = ffma2(oB.y, hr2, sr[3]);
        sz[0] = ffma2(oA.x, hz2, sz[0]); sz[1] = ffma2(oA.y, hz2, sz[1]);
        sz[2] = ffma2(oB.x, hz2, sz[2]); sz[3] = ffma2(oB.y, hz2, sz[3]);
        hn[0] = ffma2(oA.x, hn2, hn[0]); hn[1] = ffma2(oA.y, hn2, hn[1]);
        hn[2] = ffma2(oB.x, hn2, hn[2]); hn[3] = ffma2(oB.y, hn2, hn[3]);
    }

    // relu(m) -> per-warp smem staging [d][8 nodes], pitch 10
    float* msw = ms_ + w * 32 * MS_PITCH;
#pragma unroll
    for (int q = 0; q < 4; q++) {
        float2 v = unpack2(m[q]);
        v.x = fmaxf(v.x, 0.f);
        v.y = fmaxf(v.y, 0.f);
        *(float2*)&msw[d * MS_PITCH + q * 2] = v;
    }
    __syncwarp();

    // Loop B: sr/sz += m@Wih (r,z gates); inn = bih_n + m@Wih_n
    u64 inn[4];
    {
        u64 bi = splat2(sb_in[d]);
#pragma unroll
        for (int q = 0; q < 4; q++) inn[q] = bi;
    }
#pragma unroll 4
    for (int j = 0; j < 32; j++) {
        const float* mp = &msw[j * MS_PITCH];
        u64 m01 = *(const u64*)(mp + 0);
        u64 m23 = *(const u64*)(mp + 2);
        u64 m45 = *(const u64*)(mp + 4);
        u64 m67 = *(const u64*)(mp + 6);
        u64 ir2 = splat2(sWih[(0 * 32 + j) * 32 + d]);
        u64 iz2 = splat2(sWih[(1 * 32 + j) * 32 + d]);
        u64 in2 = splat2(sWih[(2 * 32 + j) * 32 + d]);
        sr[0] = ffma2(m01, ir2, sr[0]); sr[1] = ffma2(m23, ir2, sr[1]);
        sr[2] = ffma2(m45, ir2, sr[2]); sr[3] = ffma2(m67, ir2, sr[3]);
        sz[0] = ffma2(m01, iz2, sz[0]); sz[1] = ffma2(m23, iz2, sz[1]);
        sz[2] = ffma2(m45, iz2, sz[2]); sz[3] = ffma2(m67, iz2, sz[3]);
        inn[0] = ffma2(m01, in2, inn[0]); inn[1] = ffma2(m23, in2, inn[1]);
        inn[2] = ffma2(m45, in2, inn[2]); inn[3] = ffma2(m67, in2, inn[3]);
    }

    // Epilogue: GRU nonlinearity per node, write new state
#pragma unroll
    for (int q = 0; q < 4; q++) {
        float2 rs = unpack2(sr[q]);
        float2 zs = unpack2(sz[q]);
        float2 is = unpack2(inn[q]);
        float2 hs = unpack2(hn[q]);
        float2 h  = *(const float2*)&os_[d * AO_PITCH + nl + q * 2];
        int na = n0 + nl + 2 * q, nb = na + 1;
        {
            float r = sigm(rs.x), z = sigm(zs.x);
            float nn = tanh_f(fmaf(r, hs.x, is.x));
            float out = fmaf(z, h.x - nn, nn);
            if (na < N) g_state[na * DIM + f * ND + d] = out;
        }
        {
            float r = sigm(rs.y), z = sigm(zs.y);
            float nn = tanh_f(fmaf(r, hs.y, is.y));
            float out = fmaf(z, h.y - nn, nn);
            if (nb < N) g_state[nb * DIM + f * ND + d] = out;
        }
    }
}

// ------------------------- K7: segment-mean pooling ------------------------
__global__ __launch_bounds__(128) void k_pool(const int* __restrict__ batch,
                                              float* __restrict__ d_out) {
    int g = blockIdx.x;
    int c = threadIdx.x;
    int lo = 0, hi = N;
    while (lo < hi) { int mid = (lo + hi) >> 1; if (batch[mid] < g) lo = mid + 1; else hi = mid; }
    int s = lo;
    hi = N;
    while (lo < hi) { int mid = (lo + hi) >> 1; if (batch[mid] < g + 1) lo = mid + 1; else hi = mid; }
    int e = lo;
    float sum = 0.f;
    for (int n = s; n < e; n++) sum += g_state[n * DIM + c];
    float cnt = fmaxf((float)(e - s), 1.f);
    float val = __fdividef(sum, cnt);
    g_pooled[g * DIM + c] = val;
    int f = c >> 5, d = c & 31;
    d_out[OFF_OUTS + f * G * ND + g * ND + d] = val;
}

// ------------------------- K8: final MLP -----------------------------------
__global__ __launch_bounds__(128) void k_mlp(const float* __restrict__ fc1_W,
                                             const float* __restrict__ fc1_b,
                                             const float* __restrict__ fc2_W,
                                             const float* __restrict__ fc2_b,
                                             float* __restrict__ d_out) {
    __shared__ float oc[128];
    __shared__ float hid[128];
    int g = blockIdx.x, c = threadIdx.x;
    oc[c] = g_pooled[g * DIM + c];
    __syncthreads();
    float acc = fc1_b[c];
    for (int k = 0; k < DIM; k++) acc = fmaf(oc[k], fc1_W[k * DIM + c], acc);
    hid[c] = fmaxf(acc, 0.f);
    __syncthreads();
    if (c < NC) {
        float p = fc2_b[c];
        for (int k = 0; k < DIM; k++) p = fmaf(hid[k], fc2_W[k * NC + c], p);
        d_out[OFF_PRED + g * NC + c] = p;
    }
}

// ------------------------- launch ------------------------------------------
extern "C" void kernel_launch(void* const* d_in, const int* in_sizes, int n_in,
                              void* d_out_v, int out_size) {
    const float* x          = (const float*)d_in[0];
    const int*   ei         = (const int*)d_in[1];
    const int*   batch      = (const int*)d_in[2];
    const float* lin0_W     = (const float*)d_in[3];
    const float* lin0_b     = (const float*)d_in[4];
    const float* att_W      = (const float*)d_in[5];
    const float* att_b      = (const float*)d_in[6];
    const float* enc_W      = (const float*)d_in[7];
    const float* enc_b      = (const float*)d_in[8];
    const float* conv_Wrel  = (const float*)d_in[9];
    const float* conv_brel  = (const float*)d_in[10];
    const float* conv_Wroot = (const float*)d_in[11];
    const float* gru_Wih    = (const float*)d_in[12];
    const float* gru_Whh    = (const float*)d_in[13];
    const float* gru_bih    = (const float*)d_in[14];
    const float* gru_bhh    = (const float*)d_in[15];
    const float* fc1_W      = (const float*)d_in[16];
    const float* fc1_b      = (const float*)d_in[17];
    const float* fc2_W      = (const float*)d_in[18];
    const float* fc2_b      = (const float*)d_in[19];
    float* out = (float*)d_out_v;

    const int initSmem = (NF * F * ND + 2 * NF * F + F * NPB) * (int)sizeof(float);  // 77824
    cudaFuncSetAttribute(k_init, cudaFuncAttributeMaxDynamicSharedMemorySize, initSmem);
    const int updSmem = (1024 + 1024 + 3072 + 3072 + 64 + 32 + 32 + 32 +
                         2 * 32 * AO_PITCH + 8 * 32 * MS_PITCH) * (int)sizeof(float);  // 62080
    cudaFuncSetAttribute(k_update, cudaFuncAttributeMaxDynamicSharedMemorySize, updSmem);

    k_pre<<<NF, 128>>>(lin0_W, lin0_b, att_W, att_b);
    k_init<<<(N + NPB - 1) / NPB, 128, initSmem>>>(x, enc_W, enc_b);
    k_att<<<(E + 255) / 256, 256>>>(ei, out + OFF_ATT);

    k_hist<<<(E + 255) / 256, 256>>>(ei);
    k_scan<<<1, 1024>>>();
    k_scatter<<<(E + 255) / 256, 256>>>(ei);

    for (int l = 0; l < NL; l++) {
        k_agg<<<(N * 32 + 255) / 256, 256>>>();
        k_update<<<dim3((N + UPD_NPB - 1) / UPD_NPB, NF), 256, updSmem>>>(
            conv_Wrel, conv_brel, conv_Wroot,
            gru_Wih, gru_Whh, gru_bih, gru_bhh, l);
    }

    k_pool<<<G, 128>>>(batch, out);
    k_mlp<<<G, 128>>>(fc1_W, fc1_b, fc2_W, fc2_b, out);
}

// round 6
// speedup vs baseline: 1.3619x; 1.3619x over previous
#include <cuda_runtime.h>

#define DINLINE __device__ __forceinline__

constexpr int N   = 50000;
constexpr int E   = 800000;
constexpr int F   = 128;
constexpr int DIM = 128;
constexpr int NF  = 4;
constexpr int ND  = 32;
constexpr int NL  = 3;
constexpr int NC  = 10;
constexpr int G   = 256;

constexpr int OFF_PRED = 0;
constexpr int OFF_ATT  = G * NC;            // 2560
constexpr int OFF_OUTS = OFF_ATT + NF * E;  // 3202560

typedef unsigned long long u64;

// ------------------------- scratch (device globals, no cudaMalloc) ---------
__device__ float  g_state[N * DIM];
__device__ float  g_agg[N * DIM];
__device__ float  g_el[N * NF];
__device__ float  g_er[N * NF];
__device__ float  g_vl[NF * F];
__device__ float  g_vr[NF * F];
__device__ float  g_elb[NF];
__device__ float  g_erb[NF];
__device__ int    g_cnt[N];          // zero-initialized at load; k_scan re-zeroes each call
__device__ int    g_rowptr[N + 1];
__device__ int    g_fill[N];
__device__ int    g_csr_src[E];
__device__ float4 g_att_t[E];
__device__ float4 g_csr_att[E];
__device__ float  g_pooled[G * DIM];

DINLINE float sigm(float x)   { return __fdividef(1.f, 1.f + __expf(-x)); }
DINLINE float tanh_f(float x) { return 1.f - __fdividef(2.f, __expf(2.f * x) + 1.f); }

// ---- packed f32x2 helpers (FFMA2 — only reachable via PTX) ----------------
DINLINE u64 splat2(float x) { u64 r; asm("mov.b64 %0, {%1, %1};" : "=l"(r) : "f"(x)); return r; }
DINLINE float2 unpack2(u64 v) {
    float lo, hi;
    asm("mov.b64 {%0, %1}, %2;" : "=f"(lo), "=f"(hi) : "l"(v));
    return make_float2(lo, hi);
}
DINLINE u64 ffma2(u64 a, u64 b, u64 c) {
    u64 d;
    asm("fma.rn.f32x2 %0, %1, %2, %3;" : "=l"(d) : "l"(a), "l"(b), "l"(c));
    return d;
}

// ------------------------- K1: fold lin0/att into per-node vectors ---------
__global__ void k_pre(const float* __restrict__ lin0_W, const float* __restrict__ lin0_b,
                      const float* __restrict__ att_W,  const float* __restrict__ att_b) {
    int f = blockIdx.x;
    int k = threadIdx.x;
    const float* W  = lin0_W + (f * F + k) * DIM;
    const float* wl = att_W + f * 2 * DIM;
    const float* wr = wl + DIM;
    float sl = 0.f, sr = 0.f;
    for (int d = 0; d < DIM; d++) { float w = W[d]; sl = fmaf(w, wl[d], sl); sr = fmaf(w, wr[d], sr); }
    g_vl[f * F + k] = sl;
    g_vr[f * F + k] = sr;
    if (k == 0) {
        float bl = att_b[f], br = 0.f;
        const float* b0 = lin0_b + f * DIM;
        for (int d = 0; d < DIM; d++) { bl = fmaf(b0[d], wl[d], bl); br = fmaf(b0[d], wr[d], br); }
        g_elb[f] = bl;
        g_erb[f] = br;
    }
}

// ------------------------- K2: node init (enc GEMM + el/er GEMVs) ----------
constexpr int NPB = 16;  // nodes per block
__global__ __launch_bounds__(128) void k_init(const float* __restrict__ x,
                                              const float* __restrict__ enc_W,
                                              const float* __restrict__ enc_b) {
    extern __shared__ float sm[];
    float* ws = sm;                   // [k][c] : 128*128
    float* wv = ws + NF * F * ND;     // vl(512) then vr(512)
    float* xs = wv + 2 * NF * F;      // [k][NPB] : 128*16

    int tid = threadIdx.x;
    for (int i = tid; i < NF * F * ND; i += 128) {
        int c = i & 127, k = i >> 7;
        int f = c >> 5, d = c & 31;
        ws[i] = enc_W[(f * F + k) * ND + d];
    }
    for (int i = tid; i < 2 * NF * F; i += 128)
        wv[i] = (i < NF * F) ? g_vl[i] : g_vr[i - NF * F];

    int n0 = blockIdx.x * NPB;
    for (int n = 0; n < NPB; n++) {
        int node = n0 + n;
        xs[tid * NPB + n] = (node < N) ? x[node * F + tid] : 0.f;
    }
    __syncthreads();

    int c = tid;
    u64 acc2[NPB / 2];
#pragma unroll
    for (int q = 0; q < NPB / 2; q++) acc2[q] = 0ull;
    for (int k = 0; k < F; k++) {
        u64 w2 = splat2(ws[k * 128 + c]);
        const ulonglong2* xv = (const ulonglong2*)&xs[k * NPB];
#pragma unroll
        for (int q = 0; q < NPB / 4; q++) {
            ulonglong2 v = xv[q];
            acc2[q * 2 + 0] = ffma2(v.x, w2, acc2[q * 2 + 0]);
            acc2[q * 2 + 1] = ffma2(v.y, w2, acc2[q * 2 + 1]);
        }
    }
    int f = c >> 5, d = c & 31;
    float b = enc_b[f * ND + d];
#pragma unroll
    for (int q = 0; q < NPB / 2; q++) {
        float2 v = unpack2(acc2[q]);
        int na = n0 + 2 * q, nb = na + 1;
        if (na < N) g_state[na * DIM + c] = v.x + b;
        if (nb < N) g_state[nb * DIM + c] = v.y + b;
    }

    // el/er: 128 threads = 16 nodes x 8 (4 factors x {l,r})
    int nn  = tid >> 3;
    int idx = tid & 7;
    int ff  = idx & 3;
    int isR = idx >> 2;
    const float* vec = &wv[isR * NF * F + ff * F];
    float a = 0.f;
    for (int k = 0; k < F; k++) a = fmaf(xs[k * NPB + nn], vec[k], a);
    int node = n0 + nn;
    if (node < N) {
        if (isR) g_er[node * NF + ff] = a + g_erb[ff];
        else     g_el[node * NF + ff] = a + g_elb[ff];
    }
}

// ------------------------- K3: per-edge attention --------------------------
__global__ void k_att(const int* __restrict__ ei, float* __restrict__ out_att) {
    int e = blockIdx.x * blockDim.x + threadIdx.x;
    if (e >= E) return;
    int s = ei[e], d = ei[E + e];
    float4 el = *(const float4*)&g_el[s * 4];
    float4 er = *(const float4*)&g_er[d * 4];
    float4 a;
    a.x = sigm(6.f * (el.x + er.x));
    a.y = sigm(6.f * (el.y + er.y));
    a.z = sigm(6.f * (el.z + er.z));
    a.w = sigm(6.f * (el.w + er.w));
    out_att[0 * E + e] = a.x;
    out_att[1 * E + e] = a.y;
    out_att[2 * E + e] = a.z;
    out_att[3 * E + e] = a.w;
    g_att_t[e] = a;
}

// ------------------------- K4: CSR build -----------------------------------
// g_cnt starts zero (static init) and k_scan re-zeroes it after consuming,
// so the graph is replayable with identical work every call.
__global__ void k_hist(const int* __restrict__ ei) {
    int e = blockIdx.x * blockDim.x + threadIdx.x;
    if (e < E) atomicAdd(&g_cnt[ei[E + e]], 1);
}
__global__ __launch_bounds__(1024) void k_scan() {
    __shared__ int ssum[1024];
    int t = threadIdx.x;
    const int CH = (N + 1023) / 1024;  // 49
    int base = t * CH;
    int s = 0;
    for (int i = 0; i < CH; i++) { int idx = base + i; if (idx < N) s += g_cnt[idx]; }
    ssum[t] = s;
    __syncthreads();
    for (int off = 1; off < 1024; off <<= 1) {
        int v = (t >= off) ? ssum[t - off] : 0;
        __syncthreads();
        ssum[t] += v;
        __syncthreads();
    }
    int run = ssum[t] - s;  // exclusive
    for (int i = 0; i < CH; i++) {
        int idx = base + i;
        if (idx < N) {
            int c = g_cnt[idx];
            g_rowptr[idx] = run;
            g_fill[idx]   = run;
            run += c;
            g_cnt[idx] = 0;   // restore invariant for next graph replay
        }
    }
    if (t == 1023) g_rowptr[N] = ssum[1023];
}
__global__ void k_scatter(const int* __restrict__ ei) {
    int e = blockIdx.x * blockDim.x + threadIdx.x;
    if (e >= E) return;
    int s = ei[e], d = ei[E + e];
    int pos = atomicAdd(&g_fill[d], 1);
    g_csr_src[pos] = s;
    g_csr_att[pos] = g_att_t[e];
}

// ------------------------- K5: per-layer aggregation (warp per node) -------
__global__ __launch_bounds__(256) void k_agg() {
    int warp = (blockIdx.x * blockDim.x + threadIdx.x) >> 5;
    int lane = threadIdx.x & 31;
    if (warp >= N) return;
    int beg = g_rowptr[warp], end = g_rowptr[warp + 1];
    const float4* sp = (const float4*)g_state;
    int f = lane >> 3;
    float ax = 0.f, ay = 0.f, az = 0.f, aw = 0.f;
    int    src = 0;
    float4 at  = make_float4(0.f, 0.f, 0.f, 0.f);
    if (beg < end) { src = __ldg(&g_csr_src[beg]); at = g_csr_att[beg]; }
    for (int p = beg; p < end; p++) {
        int    nsrc = src;
        float4 nat  = at;
        if (p + 1 < end) { nsrc = __ldg(&g_csr_src[p + 1]); nat = g_csr_att[p + 1]; }
        float av = (f == 0) ? at.x : (f == 1) ? at.y : (f == 2) ? at.z : at.w;
        float4 v = sp[src * 32 + lane];
        ax = fmaf(av, v.x, ax);
        ay = fmaf(av, v.y, ay);
        az = fmaf(av, v.z, az);
        aw = fmaf(av, v.w, aw);
        src = nsrc;
        at  = nat;
    }
    ((float4*)g_agg)[warp * 32 + lane] = make_float4(ax, ay, az, aw);
}

// ------------------------- K6: fused conv + GRU update (f32x2, low-pressure)
// Block: 256 threads = 8 warps; each warp handles 4 nodes (lane d = output dim d).
// Block loops over UPD_CHUNKS chunks of 32 nodes, reusing SMEM weights.
// Weights are stored DUPLICATED (pair-splatted) so LDS.64 yields an f32x2
// operand directly — no mov.b64 splats in the inner loop.
// GRU algebra: r,z gates accumulate gi+gh in a single register; n gate keeps
// inn and hn separate.
constexpr int UPD_CHUNKS = 8;               // 8 x 32 = 256 nodes per block
constexpr int AO_P = 36;                    // [j][node] pitch
__global__ __launch_bounds__(256) void k_update(
    const float* __restrict__ Wrel, const float* __restrict__ brel,
    const float* __restrict__ Wroot,
    const float* __restrict__ Wih, const float* __restrict__ Whh,
    const float* __restrict__ bih, const float* __restrict__ bhh, int l) {
    extern __shared__ float sm[];
    float* sWrel2  = sm;                 // 2048 (duplicated [j][d])
    float* sWroot2 = sWrel2 + 2048;      // 2048
    float* sWih2   = sWroot2 + 2048;     // 6144 (duplicated [g][j][d])
    float* sWhh2   = sWih2 + 6144;       // 6144
    float* sb_rz2  = sWhh2 + 6144;       // 128
    float* sb_in2  = sb_rz2 + 128;       // 64
    float* sb_hn2  = sb_in2 + 64;        // 64
    float* sbrel2  = sb_hn2 + 64;        // 64
    float* as_     = sbrel2 + 64;        // 1152  [j][node] pitch 36
    float* os_     = as_ + 32 * AO_P;    // 1152
    float* ms_     = os_ + 32 * AO_P;    // 8 warps * 192

    int f   = blockIdx.y;
    int tid = threadIdx.x;

    const float* Wrel_g  = Wrel + (f * NL + l) * 1024;
    const float* Wroot_g = Wroot + (f * NL + l) * 1024;
    for (int i = tid; i < 1024; i += 256) {
        float a = Wrel_g[i], b = Wroot_g[i];
        sWrel2[2 * i] = a;  sWrel2[2 * i + 1] = a;
        sWroot2[2 * i] = b; sWroot2[2 * i + 1] = b;
    }
    const float* Wih_g = Wih + f * 3072;
    const float* Whh_g = Whh + f * 3072;
    for (int i = tid; i < 3072; i += 256) {
        int g = i >> 10, r = (i >> 5) & 31, j = i & 31;
        int t = ((g * 32 + j) * 32 + r) * 2;   // transposed: [g][j][d]
        float a = Wih_g[i], b = Whh_g[i];
        sWih2[t] = a; sWih2[t + 1] = a;
        sWhh2[t] = b; sWhh2[t + 1] = b;
    }
    if (tid < 64) {
        float v = bih[f * 96 + tid] + bhh[f * 96 + tid];
        sb_rz2[2 * tid] = v; sb_rz2[2 * tid + 1] = v;
    }
    if (tid < 32) {
        float a = bih[f * 96 + 64 + tid]; sb_in2[2 * tid] = a; sb_in2[2 * tid + 1] = a;
        float b = bhh[f * 96 + 64 + tid]; sb_hn2[2 * tid] = b; sb_hn2[2 * tid + 1] = b;
        float c = brel[(f * NL + l) * 32 + tid]; sbrel2[2 * tid] = c; sbrel2[2 * tid + 1] = c;
    }

    int w = tid >> 5, d = tid & 31, nl = w * 4;
    float* msw = ms_ + w * 192;

    for (int c = 0; c < UPD_CHUNKS; c++) {
        int n0 = (blockIdx.x * UPD_CHUNKS + c) * 32;
        __syncthreads();   // first iter: weights ready; later: protect as_/os_
        for (int u = tid; u < 1024; u += 256) {
            int j = u & 31, n = u >> 5, node = n0 + n;
            float a = 0.f, o = 0.f;
            if (node < N) {
                a = g_agg[node * DIM + f * ND + j];
                o = g_state[node * DIM + f * ND + j];
            }
            as_[j * AO_P + n] = a;
            os_[j * AO_P + n] = o;
        }
        __syncthreads();

        u64 m0, m1, sr0, sr1, sz0, sz1, hn0, hn1;
        m0 = m1 = *(const u64*)&sbrel2[2 * d];
        sr0 = sr1 = *(const u64*)&sb_rz2[2 * d];
        sz0 = sz1 = *(const u64*)&sb_rz2[64 + 2 * d];
        hn0 = hn1 = *(const u64*)&sb_hn2[2 * d];
#pragma unroll 8
        for (int j = 0; j < 32; j++) {
            ulonglong2 a2 = *(const ulonglong2*)&as_[j * AO_P + nl];
            ulonglong2 o2 = *(const ulonglong2*)&os_[j * AO_P + nl];
            u64 wr  = *(const u64*)&sWrel2[(j * 32 + d) * 2];
            u64 wo  = *(const u64*)&sWroot2[(j * 32 + d) * 2];
            u64 hr  = *(const u64*)&sWhh2[((j) * 32 + d) * 2];
            u64 hz  = *(const u64*)&sWhh2[((32 + j) * 32 + d) * 2];
            u64 hnw = *(const u64*)&sWhh2[((64 + j) * 32 + d) * 2];
            m0 = ffma2(a2.x, wr, m0);   m1 = ffma2(a2.y, wr, m1);
            m0 = ffma2(o2.x, wo, m0);   m1 = ffma2(o2.y, wo, m1);
            sr0 = ffma2(o2.x, hr, sr0); sr1 = ffma2(o2.y, hr, sr1);
            sz0 = ffma2(o2.x, hz, sz0); sz1 = ffma2(o2.y, hz, sz1);
            hn0 = ffma2(o2.x, hnw, hn0); hn1 = ffma2(o2.y, hnw, hn1);
        }
        {
            float2 v0 = unpack2(m0), v1 = unpack2(m1);
            v0.x = fmaxf(v0.x, 0.f); v0.y = fmaxf(v0.y, 0.f);
            v1.x = fmaxf(v1.x, 0.f); v1.y = fmaxf(v1.y, 0.f);
            *(float2*)&msw[d * 6]     = v0;
            *(float2*)&msw[d * 6 + 2] = v1;
        }
        __syncwarp();

        u64 i0, i1;
        i0 = i1 = *(const u64*)&sb_in2[2 * d];
#pragma unroll 8
        for (int j = 0; j < 32; j++) {
            u64 ma = *(const u64*)&msw[j * 6];
            u64 mb = *(const u64*)&msw[j * 6 + 2];
            u64 ir = *(const u64*)&sWih2[((j) * 32 + d) * 2];
            u64 iz = *(const u64*)&sWih2[((32 + j) * 32 + d) * 2];
            u64 in = *(const u64*)&sWih2[((64 + j) * 32 + d) * 2];
            sr0 = ffma2(ma, ir, sr0); sr1 = ffma2(mb, ir, sr1);
            sz0 = ffma2(ma, iz, sz0); sz1 = ffma2(mb, iz, sz1);
            i0  = ffma2(ma, in, i0);  i1  = ffma2(mb, in, i1);
        }

#pragma unroll
        for (int q = 0; q < 2; q++) {
            float2 rs = unpack2(q ? sr1 : sr0);
            float2 zs = unpack2(q ? sz1 : sz0);
            float2 is = unpack2(q ? i1 : i0);
            float2 hs = unpack2(q ? hn1 : hn0);
            float2 h  = *(const float2*)&os_[d * AO_P + nl + 2 * q];
            int na = n0 + nl + 2 * q;
            {
                float r = sigm(rs.x), z = sigm(zs.x);
                float nn = tanh_f(fmaf(r, hs.x, is.x));
                if (na < N) g_state[na * DIM + f * ND + d] = fmaf(z, h.x - nn, nn);
            }
            {
                float r = sigm(rs.y), z = sigm(zs.y);
                float nn = tanh_f(fmaf(r, hs.y, is.y));
                if (na + 1 < N) g_state[(na + 1) * DIM + f * ND + d] = fmaf(z, h.y - nn, nn);
            }
        }
    }
}

// ------------------------- K7: segment-mean pooling ------------------------
__global__ __launch_bounds__(128) void k_pool(const int* __restrict__ batch,
                                              float* __restrict__ d_out) {
    int g = blockIdx.x;
    int c = threadIdx.x;
    int lo = 0, hi = N;
    while (lo < hi) { int mid = (lo + hi) >> 1; if (batch[mid] < g) lo = mid + 1; else hi = mid; }
    int s = lo;
    hi = N;
    while (lo < hi) { int mid = (lo + hi) >> 1; if (batch[mid] < g + 1) lo = mid + 1; else hi = mid; }
    int e = lo;
    float sum = 0.f;
    for (int n = s; n < e; n++) sum += g_state[n * DIM + c];
    float cnt = fmaxf((float)(e - s), 1.f);
    float val = __fdividef(sum, cnt);
    g_pooled[g * DIM + c] = val;
    int f = c >> 5, d = c & 31;
    d_out[OFF_OUTS + f * G * ND + g * ND + d] = val;
}

// ------------------------- K8: final MLP -----------------------------------
__global__ __launch_bounds__(128) void k_mlp(const float* __restrict__ fc1_W,
                                             const float* __restrict__ fc1_b,
                                             const float* __restrict__ fc2_W,
                                             const float* __restrict__ fc2_b,
                                             float* __restrict__ d_out) {
    __shared__ float oc[128];
    __shared__ float hid[128];
    int g = blockIdx.x, c = threadIdx.x;
    oc[c] = g_pooled[g * DIM + c];
    __syncthreads();
    float acc = fc1_b[c];
    for (int k = 0; k < DIM; k++) acc = fmaf(oc[k], fc1_W[k * DIM + c], acc);
    hid[c] = fmaxf(acc, 0.f);
    __syncthreads();
    if (c < NC) {
        float p = fc2_b[c];
        for (int k = 0; k < DIM; k++) p = fmaf(hid[k], fc2_W[k * NC + c], p);
        d_out[OFF_PRED + g * NC + c] = p;
    }
}

// ------------------------- launch ------------------------------------------
extern "C" void kernel_launch(void* const* d_in, const int* in_sizes, int n_in,
                              void* d_out_v, int out_size) {
    const float* x          = (const float*)d_in[0];
    const int*   ei         = (const int*)d_in[1];
    const int*   batch      = (const int*)d_in[2];
    const float* lin0_W     = (const float*)d_in[3];
    const float* lin0_b     = (const float*)d_in[4];
    const float* att_W      = (const float*)d_in[5];
    const float* att_b      = (const float*)d_in[6];
    const float* enc_W      = (const float*)d_in[7];
    const float* enc_b      = (const float*)d_in[8];
    const float* conv_Wrel  = (const float*)d_in[9];
    const float* conv_brel  = (const float*)d_in[10];
    const float* conv_Wroot = (const float*)d_in[11];
    const float* gru_Wih    = (const float*)d_in[12];
    const float* gru_Whh    = (const float*)d_in[13];
    const float* gru_bih    = (const float*)d_in[14];
    const float* gru_bhh    = (const float*)d_in[15];
    const float* fc1_W      = (const float*)d_in[16];
    const float* fc1_b      = (const float*)d_in[17];
    const float* fc2_W      = (const float*)d_in[18];
    const float* fc2_b      = (const float*)d_in[19];
    float* out = (float*)d_out_v;

    const int initSmem = (NF * F * ND + 2 * NF * F + F * NPB) * (int)sizeof(float);  // 77824
    cudaFuncSetAttribute(k_init, cudaFuncAttributeMaxDynamicSharedMemorySize, initSmem);
    const int updSmem = (2048 + 2048 + 6144 + 6144 + 128 + 64 + 64 + 64 +
                         2 * 32 * AO_P + 8 * 192) * (int)sizeof(float);              // 82176
    cudaFuncSetAttribute(k_update, cudaFuncAttributeMaxDynamicSharedMemorySize, updSmem);

    // Order chosen so ncu's profiled launch (#3, 0-based) is k_init.
    k_hist<<<(E + 255) / 256, 256>>>(ei);
    k_scan<<<1, 1024>>>();
    k_pre<<<NF, 128>>>(lin0_W, lin0_b, att_W, att_b);
    k_init<<<(N + NPB - 1) / NPB, 128, initSmem>>>(x, enc_W, enc_b);
    k_att<<<(E + 255) / 256, 256>>>(ei, out + OFF_ATT);
    k_scatter<<<(E + 255) / 256, 256>>>(ei);

    const int updGridX = (N + UPD_CHUNKS * 32 - 1) / (UPD_CHUNKS * 32);  // 196
    for (int l = 0; l < NL; l++) {
        k_agg<<<(N * 32 + 255) / 256, 256>>>();
        k_update<<<dim3(updGridX, NF), 256, updSmem>>>(
            conv_Wrel, conv_brel, conv_Wroot,
            gru_Wih, gru_Whh, gru_bih, gru_bhh, l);
    }

    k_pool<<<G, 128>>>(batch, out);
    k_mlp<<<G, 128>>>(fc1_W, fc1_b, fc2_W, fc2_b, out);
}

// round 8
// speedup vs baseline: 1.7612x; 1.2932x over previous
#include <cuda_runtime.h>

#define DINLINE __device__ __forceinline__

constexpr int N   = 50000;
constexpr int E   = 800000;
constexpr int F   = 128;
constexpr int DIM = 128;
constexpr int NF  = 4;
constexpr int ND  = 32;
constexpr int NL  = 3;
constexpr int NC  = 10;
constexpr int G   = 256;

constexpr int OFF_PRED = 0;
constexpr int OFF_ATT  = G * NC;            // 2560
constexpr int OFF_OUTS = OFF_ATT + NF * E;  // 3202560

typedef unsigned long long u64;

// ------------------------- scratch (device globals, no cudaMalloc) ---------
__device__ float  g_state[N * DIM];
__device__ float  g_agg[N * DIM];
__device__ float  g_el[N * NF];
__device__ float  g_er[N * NF];
__device__ float  g_vl[NF * F];
__device__ float  g_vr[NF * F];
__device__ float  g_elb[NF];
__device__ float  g_erb[NF];
__device__ int    g_cnt[N];          // zero at load; k_scan re-zeroes each call
__device__ int    g_rowptr[N + 1];
__device__ int    g_fill[N];
__device__ int    g_csr_src[E];
__device__ float4 g_att_t[E];
__device__ float4 g_csr_att[E];
__device__ float  g_pooled[G * DIM];

DINLINE float sigm(float x)   { return __fdividef(1.f, 1.f + __expf(-x)); }
DINLINE float tanh_f(float x) { return 1.f - __fdividef(2.f, __expf(2.f * x) + 1.f); }

// ---- packed f32x2 helpers (FFMA2 — only reachable via PTX) ----------------
DINLINE u64 splat2(float x) { u64 r; asm("mov.b64 %0, {%1, %1};" : "=l"(r) : "f"(x)); return r; }
DINLINE float2 unpack2(u64 v) {
    float lo, hi;
    asm("mov.b64 {%0, %1}, %2;" : "=f"(lo), "=f"(hi) : "l"(v));
    return make_float2(lo, hi);
}
DINLINE u64 ffma2(u64 a, u64 b, u64 c) {
    u64 d;
    asm("fma.rn.f32x2 %0, %1, %2, %3;" : "=l"(d) : "l"(a), "l"(b), "l"(c));
    return d;
}

// ------------------------- K1: fold lin0/att into per-node vectors ---------
__global__ void k_pre(const float* __restrict__ lin0_W, const float* __restrict__ lin0_b,
                      const float* __restrict__ att_W,  const float* __restrict__ att_b) {
    int f = blockIdx.x;
    int k = threadIdx.x;
    const float* W  = lin0_W + (f * F + k) * DIM;
    const float* wl = att_W + f * 2 * DIM;
    const float* wr = wl + DIM;
    float sl = 0.f, sr = 0.f;
    for (int d = 0; d < DIM; d++) { float w = W[d]; sl = fmaf(w, wl[d], sl); sr = fmaf(w, wr[d], sr); }
    g_vl[f * F + k] = sl;
    g_vr[f * F + k] = sr;
    if (k == 0) {
        float bl = att_b[f], br = 0.f;
        const float* b0 = lin0_b + f * DIM;
        for (int d = 0; d < DIM; d++) { bl = fmaf(b0[d], wl[d], bl); br = fmaf(b0[d], wr[d], br); }
        g_elb[f] = bl;
        g_erb[f] = br;
    }
}

// ------------------------- K2: node init (enc GEMM + el/er GEMVs) ----------
// 256 threads = 2 replicas x 128 output columns; 64 nodes per block.
// Weights stream from global (L2-resident after wave 1); x staged in SMEM
// and read as warp-broadcast LDS.128. 16 f32x2 accumulators per thread.
constexpr int I_NPB   = 64;
constexpr int I_PITCH = 68;   // pad to dodge bank conflicts, keeps 16B align
__global__ __launch_bounds__(256) void k_init(const float* __restrict__ x,
                                              const float* __restrict__ enc_W,
                                              const float* __restrict__ enc_b) {
    __shared__ __align__(16) float xs[F * I_PITCH];   // 34816 B
    __shared__ float wv[2 * NF * F];                  // 4096 B

    int tid = threadIdx.x;
    int n0  = blockIdx.x * I_NPB;

    for (int i = tid; i < I_NPB * F; i += 256) {
        int n = i >> 7, k = i & 127;
        int node = n0 + n;
        xs[k * I_PITCH + n] = (node < N) ? x[node * F + k] : 0.f;
    }
    for (int i = tid; i < 2 * NF * F; i += 256)
        wv[i] = (i < NF * F) ? g_vl[i] : g_vr[i - NF * F];
    __syncthreads();

    int c = tid & 127;
    int g = tid >> 7;            // node half (32 nodes)
    int f = c >> 5, d = c & 31;
    const float* Wc = enc_W + f * F * ND + d;   // stride ND per k
    const float* xb = xs + g * 32;

    u64 acc[16];
#pragma unroll
    for (int q = 0; q < 16; q++) acc[q] = 0ull;
#pragma unroll 4
    for (int k = 0; k < F; k++) {
        u64 w2 = splat2(Wc[k * ND]);
        const ulonglong2* xv = (const ulonglong2*)(xb + k * I_PITCH);
#pragma unroll
        for (int q = 0; q < 8; q++) {
            ulonglong2 v = xv[q];
            acc[2 * q]     = ffma2(v.x, w2, acc[2 * q]);
            acc[2 * q + 1] = ffma2(v.y, w2, acc[2 * q + 1]);
        }
    }
    float b = enc_b[f * ND + d];
#pragma unroll
    for (int q = 0; q < 16; q++) {
        float2 v = unpack2(acc[q]);
        int na = n0 + g * 32 + 2 * q;
        if (na < N)     g_state[na * DIM + c]       = v.x + b;
        if (na + 1 < N) g_state[(na + 1) * DIM + c] = v.y + b;
    }

    // el/er: 64 nodes x 8 combos = 512 tasks, 2 per thread
#pragma unroll
    for (int rep = 0; rep < 2; rep++) {
        int t = tid + rep * 256;
        int n = t >> 3;
        int combo = t & 7;
        int ff = combo & 3, isR = combo >> 2;
        const float* vec = &wv[isR * NF * F + ff * F];
        float a = 0.f;
        for (int k = 0; k < F; k++) a = fmaf(xs[k * I_PITCH + n], vec[k], a);
        int node = n0 + n;
        if (node < N) {
            if (isR) g_er[node * NF + ff] = a + g_erb[ff];
            else     g_el[node * NF + ff] = a + g_elb[ff];
        }
    }
}

// ------------------------- K3: per-edge attention --------------------------
__global__ void k_att(const int* __restrict__ ei, float* __restrict__ out_att) {
    int e = blockIdx.x * blockDim.x + threadIdx.x;
    if (e >= E) return;
    int s = ei[e], d = ei[E + e];
    float4 el = *(const float4*)&g_el[s * 4];
    float4 er = *(const float4*)&g_er[d * 4];
    float4 a;
    a.x = sigm(6.f * (el.x + er.x));
    a.y = sigm(6.f * (el.y + er.y));
    a.z = sigm(6.f * (el.z + er.z));
    a.w = sigm(6.f * (el.w + er.w));
    out_att[0 * E + e] = a.x;
    out_att[1 * E + e] = a.y;
    out_att[2 * E + e] = a.z;
    out_att[3 * E + e] = a.w;
    g_att_t[e] = a;
}

// ------------------------- K4: CSR build -----------------------------------
__global__ void k_hist(const int* __restrict__ ei) {
    int e = blockIdx.x * blockDim.x + threadIdx.x;
    if (e < E) atomicAdd(&g_cnt[ei[E + e]], 1);
}
__global__ __launch_bounds__(1024) void k_scan() {
    __shared__ int ssum[1024];
    int t = threadIdx.x;
    const int CH = (N + 1023) / 1024;  // 49
    int base = t * CH;
    int s = 0;
    for (int i = 0; i < CH; i++) { int idx = base + i; if (idx < N) s += g_cnt[idx]; }
    ssum[t] = s;
    __syncthreads();
    for (int off = 1; off < 1024; off <<= 1) {
        int v = (t >= off) ? ssum[t - off] : 0;
        __syncthreads();
        ssum[t] += v;
        __syncthreads();
    }
    int run = ssum[t] - s;  // exclusive
    for (int i = 0; i < CH; i++) {
        int idx = base + i;
        if (idx < N) {
            int c = g_cnt[idx];
            g_rowptr[idx] = run;
            g_fill[idx]   = run;
            run += c;
            g_cnt[idx] = 0;   // restore for graph replay
        }
    }
    if (t == 1023) g_rowptr[N] = ssum[1023];
}
__global__ void k_scatter(const int* __restrict__ ei) {
    int e = blockIdx.x * blockDim.x + threadIdx.x;
    if (e >= E) return;
    int s = ei[e], d = ei[E + e];
    int pos = atomicAdd(&g_fill[d], 1);
    g_csr_src[pos] = s;
    g_csr_att[pos] = g_att_t[e];
}

// ------------------------- K5: per-layer aggregation (warp per node) -------
__global__ __launch_bounds__(256) void k_agg() {
    int warp = (blockIdx.x * blockDim.x + threadIdx.x) >> 5;
    int lane = threadIdx.x & 31;
    if (warp >= N) return;
    int beg = g_rowptr[warp], end = g_rowptr[warp + 1];
    const float4* sp = (const float4*)g_state;
    int f = lane >> 3;
    float ax = 0.f, ay = 0.f, az = 0.f, aw = 0.f;
    int    src = 0;
    float4 at  = make_float4(0.f, 0.f, 0.f, 0.f);
    if (beg < end) { src = __ldg(&g_csr_src[beg]); at = g_csr_att[beg]; }
    for (int p = beg; p < end; p++) {
        int    nsrc = src;
        float4 nat  = at;
        if (p + 1 < end) { nsrc = __ldg(&g_csr_src[p + 1]); nat = g_csr_att[p + 1]; }
        float av = (f == 0) ? at.x : (f == 1) ? at.y : (f == 2) ? at.z : at.w;
        float4 v = sp[src * 32 + lane];
        ax = fmaf(av, v.x, ax);
        ay = fmaf(av, v.y, ay);
        az = fmaf(av, v.z, az);
        aw = fmaf(av, v.w, aw);
        src = nsrc;
        at  = nat;
    }
    ((float4*)g_agg)[warp * 32 + lane] = make_float4(ax, ay, az, aw);
}

// ------------------------- K6: fused conv + GRU update ---------------------
// 256 threads = 8 warps; each warp handles 8 nodes (lane d = output dim).
// 4 chunks of 64 nodes per block (weights staged once, scalar LDS.32 + splat:
// 1 smem wavefront per weight per warp, each feeding 8 nodes of FFMA2).
constexpr int UPD_CHUNKS = 4;               // 4 x 64 = 256 nodes per block
constexpr int AO_P = 68;                    // [j][node] pitch (64 + pad)
__global__ __launch_bounds__(256) void k_update(
    const float* __restrict__ Wrel, const float* __restrict__ brel,
    const float* __restrict__ Wroot,
    const float* __restrict__ Wih, const float* __restrict__ Whh,
    const float* __restrict__ bih, const float* __restrict__ bhh, int l) {
    extern __shared__ float sm[];
    float* sWrel  = sm;                  // 1024  [j][d]
    float* sWroot = sWrel + 1024;        // 1024  [j][d]
    float* sWih   = sWroot + 1024;       // 3072  [g][j][d]
    float* sWhh   = sWih + 3072;         // 3072  [g][j][d]
    float* sb_rz  = sWhh + 3072;         // 64
    float* sb_in  = sb_rz + 64;          // 32
    float* sb_hn  = sb_in + 32;          // 32
    float* sbrel  = sb_hn + 32;          // 32
    float* as_    = sbrel + 32;          // 2176  [j][node] pitch 68
    float* os_    = as_ + 32 * AO_P;     // 2176
    float* ms_    = os_ + 32 * AO_P;     // 8 warps * 320

    int f   = blockIdx.y;
    int tid = threadIdx.x;

    const float* Wrel_g  = Wrel + (f * NL + l) * 1024;
    const float* Wroot_g = Wroot + (f * NL + l) * 1024;
    for (int i = tid; i < 1024; i += 256) { sWrel[i] = Wrel_g[i]; sWroot[i] = Wroot_g[i]; }
    const float* Wih_g = Wih + f * 3072;
    const float* Whh_g = Whh + f * 3072;
    for (int i = tid; i < 3072; i += 256) {
        int g = i >> 10, r = (i >> 5) & 31, j = i & 31;
        int t = (g * 32 + j) * 32 + r;   // transposed: [g][j][d]
        sWih[t] = Wih_g[i];
        sWhh[t] = Whh_g[i];
    }
    if (tid < 64) sb_rz[tid] = bih[f * 96 + tid] + bhh[f * 96 + tid];
    if (tid < 32) {
        sb_in[tid] = bih[f * 96 + 64 + tid];
        sb_hn[tid] = bhh[f * 96 + 64 + tid];
        sbrel[tid] = brel[(f * NL + l) * 32 + tid];
    }

    int w = tid >> 5, d = tid & 31, nl = w * 8;
    float* msw = ms_ + w * 320;

    for (int c = 0; c < UPD_CHUNKS; c++) {
        int n0 = (blockIdx.x * UPD_CHUNKS + c) * 64;
        __syncthreads();   // weights ready (1st) / protect as_, os_, ms_ (rest)
        for (int u = tid; u < 2048; u += 256) {
            int j = u & 31, n = u >> 5, node = n0 + n;
            float a = 0.f, o = 0.f;
            if (node < N) {
                a = g_agg[node * DIM + f * ND + j];
                o = g_state[node * DIM + f * ND + j];
            }
            as_[j * AO_P + n] = a;
            os_[j * AO_P + n] = o;
        }
        __syncthreads();

        u64 m[4], sr[4], sz[4], hn[4];
        {
            u64 bm = splat2(sbrel[d]);
            u64 br = splat2(sb_rz[d]);
            u64 bz = splat2(sb_rz[32 + d]);
            u64 bn = splat2(sb_hn[d]);
#pragma unroll
            for (int q = 0; q < 4; q++) { m[q] = bm; sr[q] = br; sz[q] = bz; hn[q] = bn; }
        }
#pragma unroll 2
        for (int j = 0; j < 32; j++) {
            ulonglong2 aA = *(const ulonglong2*)&as_[j * AO_P + nl];
            ulonglong2 aB = *(const ulonglong2*)&as_[j * AO_P + nl + 4];
            ulonglong2 oA = *(const ulonglong2*)&os_[j * AO_P + nl];
            ulonglong2 oB = *(const ulonglong2*)&os_[j * AO_P + nl + 4];
            u64 wr  = splat2(sWrel[j * 32 + d]);
            u64 wo  = splat2(sWroot[j * 32 + d]);
            u64 hr  = splat2(sWhh[j * 32 + d]);
            u64 hz  = splat2(sWhh[(32 + j) * 32 + d]);
            u64 hnw = splat2(sWhh[(64 + j) * 32 + d]);
            m[0] = ffma2(aA.x, wr, m[0]);  m[1] = ffma2(aA.y, wr, m[1]);
            m[2] = ffma2(aB.x, wr, m[2]);  m[3] = ffma2(aB.y, wr, m[3]);
            m[0] = ffma2(oA.x, wo, m[0]);  m[1] = ffma2(oA.y, wo, m[1]);
            m[2] = ffma2(oB.x, wo, m[2]);  m[3] = ffma2(oB.y, wo, m[3]);
            sr[0] = ffma2(oA.x, hr, sr[0]); sr[1] = ffma2(oA.y, hr, sr[1]);
            sr[2] = ffma2(oB.x, hr, sr[2]); sr[3] = ffma2(oB.y, hr, sr[3]);
            sz[0] = ffma2(oA.x, hz, sz[0]); sz[1] = ffma2(oA.y, hz, sz[1]);
            sz[2] = ffma2(oB.x, hz, sz[2]); sz[3] = ffma2(oB.y, hz, sz[3]);
            hn[0] = ffma2(oA.x, hnw, hn[0]); hn[1] = ffma2(oA.y, hnw, hn[1]);
            hn[2] = ffma2(oB.x, hnw, hn[2]); hn[3] = ffma2(oB.y, hnw, hn[3]);
        }
#pragma unroll
        for (int q = 0; q < 4; q++) {
            float2 v = unpack2(m[q]);
            v.x = fmaxf(v.x, 0.f);
            v.y = fmaxf(v.y, 0.f);
            *(float2*)&msw[d * 10 + 2 * q] = v;
        }
        __syncwarp();

        u64 inn[4];
        {
            u64 bi = splat2(sb_in[d]);
#pragma unroll
            for (int q = 0; q < 4; q++) inn[q] = bi;
        }
#pragma unroll 2
        for (int j = 0; j < 32; j++) {
            u64 m01 = *(const u64*)&msw[j * 10];
            u64 m23 = *(const u64*)&msw[j * 10 + 2];
            u64 m45 = *(const u64*)&msw[j * 10 + 4];
            u64 m67 = *(const u64*)&msw[j * 10 + 6];
            u64 ir = splat2(sWih[j * 32 + d]);
            u64 iz = splat2(sWih[(32 + j) * 32 + d]);
            u64 in2 = splat2(sWih[(64 + j) * 32 + d]);
            sr[0] = ffma2(m01, ir, sr[0]); sr[1] = ffma2(m23, ir, sr[1]);
            sr[2] = ffma2(m45, ir, sr[2]); sr[3] = ffma2(m67, ir, sr[3]);
            sz[0] = ffma2(m01, iz, sz[0]); sz[1] = ffma2(m23, iz, sz[1]);
            sz[2] = ffma2(m45, iz, sz[2]); sz[3] = ffma2(m67, iz, sz[3]);
            inn[0] = ffma2(m01, in2, inn[0]); inn[1] = ffma2(m23, in2, inn[1]);
            inn[2] = ffma2(m45, in2, inn[2]); inn[3] = ffma2(m67, in2, inn[3]);
        }

#pragma unroll
        for (int q = 0; q < 4; q++) {
            float2 rs = unpack2(sr[q]);
            float2 zs = unpack2(sz[q]);
            float2 is = unpack2(inn[q]);
            float2 hs = unpack2(hn[q]);
            float2 h  = *(const float2*)&os_[d * AO_P + nl + 2 * q];
            int na = n0 + nl + 2 * q;
            {
                float r = sigm(rs.x), z = sigm(zs.x);
                float nn = tanh_f(fmaf(r, hs.x, is.x));
                if (na < N) g_state[na * DIM + f * ND + d] = fmaf(z, h.x - nn, nn);
            }
            {
                float r = sigm(rs.y), z = sigm(zs.y);
                float nn = tanh_f(fmaf(r, hs.y, is.y));
                if (na + 1 < N) g_state[(na + 1) * DIM + f * ND + d] = fmaf(z, h.y - nn, nn);
            }
        }
    }
}

// ------------------------- K7: segment-mean pooling ------------------------
__global__ __launch_bounds__(128) void k_pool(const int* __restrict__ batch,
                                              float* __restrict__ d_out) {
    int g = blockIdx.x;
    int c = threadIdx.x;
    int lo = 0, hi = N;
    while (lo < hi) { int mid = (lo + hi) >> 1; if (batch[mid] < g) lo = mid + 1; else hi = mid; }
    int s = lo;
    hi = N;
    while (lo < hi) { int mid = (lo + hi) >> 1; if (batch[mid] < g + 1) lo = mid + 1; else hi = mid; }
    int e = lo;
    float sum = 0.f;
    for (int n = s; n < e; n++) sum += g_state[n * DIM + c];
    float cnt = fmaxf((float)(e - s), 1.f);
    float val = __fdividef(sum, cnt);
    g_pooled[g * DIM + c] = val;
    int f = c >> 5, d = c & 31;
    d_out[OFF_OUTS + f * G * ND + g * ND + d] = val;
}

// ------------------------- K8: final MLP -----------------------------------
__global__ __launch_bounds__(128) void k_mlp(const float* __restrict__ fc1_W,
                                             const float* __restrict__ fc1_b,
                                             const float* __restrict__ fc2_W,
                                             const float* __restrict__ fc2_b,
                                             float* __restrict__ d_out) {
    __shared__ float oc[128];
    __shared__ float hid[128];
    int g = blockIdx.x, c = threadIdx.x;
    oc[c] = g_pooled[g * DIM + c];
    __syncthreads();
    float acc = fc1_b[c];
    for (int k = 0; k < DIM; k++) acc = fmaf(oc[k], fc1_W[k * DIM + c], acc);
    hid[c] = fmaxf(acc, 0.f);
    __syncthreads();
    if (c < NC) {
        float p = fc2_b[c];
        for (int k = 0; k < DIM; k++) p = fmaf(hid[k], fc2_W[k * NC + c], p);
        d_out[OFF_PRED + g * NC + c] = p;
    }
}

// ------------------------- launch ------------------------------------------
extern "C" void kernel_launch(void* const* d_in, const int* in_sizes, int n_in,
                              void* d_out_v, int out_size) {
    const float* x          = (const float*)d_in[0];
    const int*   ei         = (const int*)d_in[1];
    const int*   batch      = (const int*)d_in[2];
    const float* lin0_W     = (const float*)d_in[3];
    const float* lin0_b     = (const float*)d_in[4];
    const float* att_W      = (const float*)d_in[5];
    const float* att_b      = (const float*)d_in[6];
    const float* enc_W      = (const float*)d_in[7];
    const float* enc_b      = (const float*)d_in[8];
    const float* conv_Wrel  = (const float*)d_in[9];
    const float* conv_brel  = (const float*)d_in[10];
    const float* conv_Wroot = (const float*)d_in[11];
    const float* gru_Wih    = (const float*)d_in[12];
    const float* gru_Whh    = (const float*)d_in[13];
    const float* gru_bih    = (const float*)d_in[14];
    const float* gru_bhh    = (const float*)d_in[15];
    const float* fc1_W      = (const float*)d_in[16];
    const float* fc1_b      = (const float*)d_in[17];
    const float* fc2_W      = (const float*)d_in[18];
    const float* fc2_b      = (const float*)d_in[19];
    float* out = (float*)d_out_v;

    const int updSmem = (1024 + 1024 + 3072 + 3072 + 64 + 32 + 32 + 32 +
                         2 * 32 * AO_P + 8 * 320) * (int)sizeof(float);  // 61056
    cudaFuncSetAttribute(k_update, cudaFuncAttributeMaxDynamicSharedMemorySize, updSmem);

    // Order keeps k_init as the ncu-profiled launch (#4).
    k_hist<<<(E + 255) / 256, 256>>>(ei);
    k_scan<<<1, 1024>>>();
    k_pre<<<NF, 128>>>(lin0_W, lin0_b, att_W, att_b);
    k_init<<<(N + I_NPB - 1) / I_NPB, 256>>>(x, enc_W, enc_b);
    k_att<<<(E + 255) / 256, 256>>>(ei, out + OFF_ATT);
    k_scatter<<<(E + 255) / 256, 256>>>(ei);

    const int updGridX = (N + UPD_CHUNKS * 64 - 1) / (UPD_CHUNKS * 64);  // 196
    for (int l = 0; l < NL; l++) {
        k_agg<<<(N * 32 + 255) / 256, 256>>>();
        k_update<<<dim3(updGridX, NF), 256, updSmem>>>(
            conv_Wrel, conv_brel, conv_Wroot,
            gru_Wih, gru_Whh, gru_bih, gru_bhh, l);
    }

    k_pool<<<G, 128>>>(batch, out);
    k_mlp<<<G, 128>>>(fc1_W, fc1_b, fc2_W, fc2_b, out);
}

// round 12
// speedup vs baseline: 1.7891x; 1.0159x over previous
#include <cuda_runtime.h>

#define DINLINE __device__ __forceinline__

constexpr int N   = 50000;
constexpr int E   = 800000;
constexpr int F   = 128;
constexpr int DIM = 128;
constexpr int NF  = 4;
constexpr int ND  = 32;
constexpr int NL  = 3;
constexpr int NC  = 10;
constexpr int G   = 256;

constexpr int OFF_PRED = 0;
constexpr int OFF_ATT  = G * NC;            // 2560
constexpr int OFF_OUTS = OFF_ATT + NF * E;  // 3202560

typedef unsigned long long u64;

// ------------------------- scratch (device globals, no cudaMalloc) ---------
__device__ float  g_state[N * DIM];
__device__ float  g_agg[N * DIM];
__device__ float  g_el[N * NF];
__device__ float  g_er[N * NF];
__device__ float  g_vl[NF * F];
__device__ float  g_vr[NF * F];
__device__ float  g_elb[NF];
__device__ float  g_erb[NF];
__device__ int    g_cnt[N];          // zero at load; k_scan re-zeroes each call
__device__ int    g_rowptr[N + 1];
__device__ int    g_fill[N];
__device__ int    g_csr_src[E];
__device__ float4 g_csr_att[E];
__device__ float  g_pooled[G * DIM];

DINLINE float sigm(float x)   { return __fdividef(1.f, 1.f + __expf(-x)); }
DINLINE float tanh_f(float x) { return 1.f - __fdividef(2.f, __expf(2.f * x) + 1.f); }

// ---- packed f32x2 helpers (FFMA2 — only reachable via PTX) ----------------
DINLINE u64 splat2(float x) { u64 r; asm("mov.b64 %0, {%1, %1};" : "=l"(r) : "f"(x)); return r; }
DINLINE float2 unpack2(u64 v) {
    float lo, hi;
    asm("mov.b64 {%0, %1}, %2;" : "=f"(lo), "=f"(hi) : "l"(v));
    return make_float2(lo, hi);
}
DINLINE u64 ffma2(u64 a, u64 b, u64 c) {
    u64 d;
    asm("fma.rn.f32x2 %0, %1, %2, %3;" : "=l"(d) : "l"(a), "l"(b), "l"(c));
    return d;
}

// ------------------------- K1: fold lin0/att into per-node vectors ---------
__global__ void k_pre(const float* __restrict__ lin0_W, const float* __restrict__ lin0_b,
                      const float* __restrict__ att_W,  const float* __restrict__ att_b) {
    int f = blockIdx.x;
    int k = threadIdx.x;
    const float* W  = lin0_W + (f * F + k) * DIM;
    const float* wl = att_W + f * 2 * DIM;
    const float* wr = wl + DIM;
    float sl = 0.f, sr = 0.f;
    for (int d = 0; d < DIM; d++) { float w = W[d]; sl = fmaf(w, wl[d], sl); sr = fmaf(w, wr[d], sr); }
    g_vl[f * F + k] = sl;
    g_vr[f * F + k] = sr;
    if (k == 0) {
        float bl = att_b[f], br = 0.f;
        const float* b0 = lin0_b + f * DIM;
        for (int d = 0; d < DIM; d++) { bl = fmaf(b0[d], wl[d], bl); br = fmaf(b0[d], wr[d], br); }
        g_elb[f] = bl;
        g_erb[f] = br;
    }
}

// ------------------------- K2: node init (enc GEMM + el/er GEMVs) ----------
// Outer-product register tile: 256 threads; thread = (col-group cg of 4 cols,
// node-group ng of 8 nodes). Per k: 1 coalesced LDG.128 (4 weights) +
// 2 broadcast LDS.128 (8 node vals) -> 16 FFMA2. FMA-bound by design.
constexpr int I_NPB   = 64;
constexpr int I_PITCH = 68;
__global__ __launch_bounds__(256) void k_init(const float* __restrict__ x,
                                              const float* __restrict__ enc_W,
                                              const float* __restrict__ enc_b) {
    __shared__ __align__(16) float xs[F * I_PITCH];   // [k][n] 34816 B
    __shared__ float wv[2 * NF * F];                  // 4096 B

    int tid = threadIdx.x;
    int n0  = blockIdx.x * I_NPB;

    for (int i = tid; i < I_NPB * F; i += 256) {
        int n = i >> 7, k = i & 127;
        int node = n0 + n;
        xs[k * I_PITCH + n] = (node < N) ? x[node * F + k] : 0.f;
    }
    for (int i = tid; i < 2 * NF * F; i += 256)
        wv[i] = (i < NF * F) ? g_vl[i] : g_vr[i - NF * F];
    __syncthreads();

    int cg = tid & 31, ng = tid >> 5;
    int c0 = cg * 4;
    int f  = c0 >> 5, d0 = c0 & 31;
    const float4* Wp = (const float4*)(enc_W + f * F * ND + d0);  // +k*8 float4 per k
    const float*  xb = xs + ng * 8;

    u64 acc[4][4];
#pragma unroll
    for (int i = 0; i < 4; i++)
#pragma unroll
        for (int q = 0; q < 4; q++) acc[i][q] = 0ull;

#pragma unroll 4
    for (int k = 0; k < F; k++) {
        float4 w4 = Wp[k * (ND / 4)];
        u64 w0 = splat2(w4.x), w1 = splat2(w4.y), w2 = splat2(w4.z), w3 = splat2(w4.w);
        ulonglong2 xA = *(const ulonglong2*)(xb + k * I_PITCH);
        ulonglong2 xB = *(const ulonglong2*)(xb + k * I_PITCH + 4);
        acc[0][0] = ffma2(xA.x, w0, acc[0][0]); acc[0][1] = ffma2(xA.y, w0, acc[0][1]);
        acc[0][2] = ffma2(xB.x, w0, acc[0][2]); acc[0][3] = ffma2(xB.y, w0, acc[0][3]);
        acc[1][0] = ffma2(xA.x, w1, acc[1][0]); acc[1][1] = ffma2(xA.y, w1, acc[1][1]);
        acc[1][2] = ffma2(xB.x, w1, acc[1][2]); acc[1][3] = ffma2(xB.y, w1, acc[1][3]);
        acc[2][0] = ffma2(xA.x, w2, acc[2][0]); acc[2][1] = ffma2(xA.y, w2, acc[2][1]);
        acc[2][2] = ffma2(xB.x, w2, acc[2][2]); acc[2][3] = ffma2(xB.y, w2, acc[2][3]);
        acc[3][0] = ffma2(xA.x, w3, acc[3][0]); acc[3][1] = ffma2(xA.y, w3, acc[3][1]);
        acc[3][2] = ffma2(xB.x, w3, acc[3][2]); acc[3][3] = ffma2(xB.y, w3, acc[3][3]);
    }

    float4 b4 = *(const float4*)&enc_b[f * ND + d0];
#pragma unroll
    for (int q = 0; q < 4; q++) {
        float2 v0 = unpack2(acc[0][q]);
        float2 v1 = unpack2(acc[1][q]);
        float2 v2 = unpack2(acc[2][q]);
        float2 v3 = unpack2(acc[3][q]);
        int na = n0 + ng * 8 + 2 * q;
        if (na < N)
            *(float4*)&g_state[na * DIM + c0] =
                make_float4(v0.x + b4.x, v1.x + b4.y, v2.x + b4.z, v3.x + b4.w);
        if (na + 1 < N)
            *(float4*)&g_state[(na + 1) * DIM + c0] =
                make_float4(v0.y + b4.x, v1.y + b4.y, v2.y + b4.z, v3.y + b4.w);
    }

    // el/er: 64 nodes x 8 combos = 512 tasks, 2 per thread
#pragma unroll
    for (int rep = 0; rep < 2; rep++) {
        int t = tid + rep * 256;
        int n = t >> 3;
        int combo = t & 7;
        int ff = combo & 3, isR = combo >> 2;
        const float* vec = &wv[isR * NF * F + ff * F];
        float a = 0.f;
        for (int k = 0; k < F; k++) a = fmaf(xs[k * I_PITCH + n], vec[k], a);
        int node = n0 + n;
        if (node < N) {
            if (isR) g_er[node * NF + ff] = a + g_erb[ff];
            else     g_el[node * NF + ff] = a + g_elb[ff];
        }
    }
}

// ------------------------- K3: CSR build (hist + scan) ---------------------
__global__ void k_hist(const int* __restrict__ ei) {
    int e = blockIdx.x * blockDim.x + threadIdx.x;
    if (e < E) atomicAdd(&g_cnt[ei[E + e]], 1);
}
__global__ __launch_bounds__(1024) void k_scan() {
    __shared__ int ssum[1024];
    int t = threadIdx.x;
    const int CH = (N + 1023) / 1024;  // 49
    int base = t * CH;
    int s = 0;
    for (int i = 0; i < CH; i++) { int idx = base + i; if (idx < N) s += g_cnt[idx]; }
    ssum[t] = s;
    __syncthreads();
    for (int off = 1; off < 1024; off <<= 1) {
        int v = (t >= off) ? ssum[t - off] : 0;
        __syncthreads();
        ssum[t] += v;
        __syncthreads();
    }
    int run = ssum[t] - s;  // exclusive
    for (int i = 0; i < CH; i++) {
        int idx = base + i;
        if (idx < N) {
            int c = g_cnt[idx];
            g_rowptr[idx] = run;
            g_fill[idx]   = run;
            run += c;
            g_cnt[idx] = 0;   // restore for graph replay
        }
    }
    if (t == 1023) g_rowptr[N] = ssum[1023];
}

// ------------------------- K4: fused attention + CSR scatter ---------------
__global__ void k_attscat(const int* __restrict__ ei, float* __restrict__ out_att) {
    int e = blockIdx.x * blockDim.x + threadIdx.x;
    if (e >= E) return;
    int s = ei[e], d = ei[E + e];
    float4 el = *(const float4*)&g_el[s * 4];
    float4 er = *(const float4*)&g_er[d * 4];
    float4 a;
    a.x = sigm(6.f * (el.x + er.x));
    a.y = sigm(6.f * (el.y + er.y));
    a.z = sigm(6.f * (el.z + er.z));
    a.w = sigm(6.f * (el.w + er.w));
    out_att[0 * E + e] = a.x;
    out_att[1 * E + e] = a.y;
    out_att[2 * E + e] = a.z;
    out_att[3 * E + e] = a.w;
    int pos = atomicAdd(&g_fill[d], 1);
    g_csr_src[pos] = s;
    g_csr_att[pos] = a;
}

// ------------------------- K5: per-layer aggregation (warp per node) -------
__global__ __launch_bounds__(256) void k_agg() {
    int warp = (blockIdx.x * blockDim.x + threadIdx.x) >> 5;
    int lane = threadIdx.x & 31;
    if (warp >= N) return;
    int beg = g_rowptr[warp], end = g_rowptr[warp + 1];
    const float4* sp = (const float4*)g_state;
    int f = lane >> 3;
    float ax = 0.f, ay = 0.f, az = 0.f, aw = 0.f;
    int    src = 0;
    float4 at  = make_float4(0.f, 0.f, 0.f, 0.f);
    if (beg < end) { src = __ldg(&g_csr_src[beg]); at = g_csr_att[beg]; }
    for (int p = beg; p < end; p++) {
        int    nsrc = src;
        float4 nat  = at;
        if (p + 1 < end) { nsrc = __ldg(&g_csr_src[p + 1]); nat = g_csr_att[p + 1]; }
        float av = (f == 0) ? at.x : (f == 1) ? at.y : (f == 2) ? at.z : at.w;
        float4 v = sp[src * 32 + lane];
        ax = fmaf(av, v.x, ax);
        ay = fmaf(av, v.y, ay);
        az = fmaf(av, v.z, az);
        aw = fmaf(av, v.w, aw);
        src = nsrc;
        at  = nat;
    }
    ((float4*)g_agg)[warp * 32 + lane] = make_float4(ax, ay, az, aw);
}

// ------------------------- K6: fused conv + GRU update ---------------------
// 256 threads = 8 warps; each warp handles 16 nodes (lane d = output dim).
// 2 chunks of 128 nodes per block. Scalar LDS.32 weight + splat (1 wavefront
// feeding 16 nodes of FFMA2) -> FMA-pipe-bound.
constexpr int UPD_CHUNKS = 2;               // 2 x 128 = 256 nodes per block
constexpr int AO_P  = 132;                  // [j][node] pitch (128 + pad, 16B-aligned)
constexpr int MS_P  = 20;                   // per-warp m staging pitch (16 + pad)
__global__ __launch_bounds__(256) void k_update(
    const float* __restrict__ Wrel, const float* __restrict__ brel,
    const float* __restrict__ Wroot,
    const float* __restrict__ Wih, const float* __restrict__ Whh,
    const float* __restrict__ bih, const float* __restrict__ bhh, int l) {
    extern __shared__ float sm[];
    float* sWrel  = sm;                  // 1024  [j][d]
    float* sWroot = sWrel + 1024;        // 1024  [j][d]
    float* sWih   = sWroot + 1024;       // 3072  [g][j][d]
    float* sWhh   = sWih + 3072;         // 3072  [g][j][d]
    float* sb_rz  = sWhh + 3072;         // 64
    float* sb_in  = sb_rz + 64;          // 32
    float* sb_hn  = sb_in + 32;          // 32
    float* sbrel  = sb_hn + 32;          // 32
    float* as_    = sbrel + 32;          // 4224  [j][node] pitch 132
    float* os_    = as_ + 32 * AO_P;     // 4224
    float* ms_    = os_ + 32 * AO_P;     // 8 warps * 32*20 = 5120

    int f   = blockIdx.y;
    int tid = threadIdx.x;

    const float* Wrel_g  = Wrel + (f * NL + l) * 1024;
    const float* Wroot_g = Wroot + (f * NL + l) * 1024;
    for (int i = tid; i < 1024; i += 256) { sWrel[i] = Wrel_g[i]; sWroot[i] = Wroot_g[i]; }
    const float* Wih_g = Wih + f * 3072;
    const float* Whh_g = Whh + f * 3072;
    for (int i = tid; i < 3072; i += 256) {
        int g = i >> 10, r = (i >> 5) & 31, j = i & 31;
        int t = (g * 32 + j) * 32 + r;   // transposed: [g][j][d]
        sWih[t] = Wih_g[i];
        sWhh[t] = Whh_g[i];
    }
    if (tid < 64) sb_rz[tid] = bih[f * 96 + tid] + bhh[f * 96 + tid];
    if (tid < 32) {
        sb_in[tid] = bih[f * 96 + 64 + tid];
        sb_hn[tid] = bhh[f * 96 + 64 + tid];
        sbrel[tid] = brel[(f * NL + l) * 32 + tid];
    }

    int w = tid >> 5, d = tid & 31, nl = w * 16;
    float* msw = ms_ + w * 32 * MS_P;

    for (int c = 0; c < UPD_CHUNKS; c++) {
        int n0 = (blockIdx.x * UPD_CHUNKS + c) * 128;
        __syncthreads();   // weights ready (1st) / protect as_, os_, ms_ (rest)
        for (int u = tid; u < 4096; u += 256) {
            int j = u & 31, n = u >> 5, node = n0 + n;
            float a = 0.f, o = 0.f;
            if (node < N) {
                a = g_agg[node * DIM + f * ND + j];
                o = g_state[node * DIM + f * ND + j];
            }
            as_[j * AO_P + n] = a;
            os_[j * AO_P + n] = o;
        }
        __syncthreads();

        u64 m[8], sr[8], sz[8], hn[8];
        {
            u64 bm = splat2(sbrel[d]);
            u64 br = splat2(sb_rz[d]);
            u64 bz = splat2(sb_rz[32 + d]);
            u64 bn = splat2(sb_hn[d]);
#pragma unroll
            for (int q = 0; q < 8; q++) { m[q] = bm; sr[q] = br; sz[q] = bz; hn[q] = bn; }
        }
#pragma unroll 2
        for (int j = 0; j < 32; j++) {
            u64 wr  = splat2(sWrel[j * 32 + d]);
            u64 wo  = splat2(sWroot[j * 32 + d]);
            u64 hr  = splat2(sWhh[j * 32 + d]);
            u64 hz  = splat2(sWhh[(32 + j) * 32 + d]);
            u64 hnw = splat2(sWhh[(64 + j) * 32 + d]);
#pragma unroll
            for (int h = 0; h < 4; h++) {
                ulonglong2 a2 = *(const ulonglong2*)&as_[j * AO_P + nl + 4 * h];
                ulonglong2 o2 = *(const ulonglong2*)&os_[j * AO_P + nl + 4 * h];
                m[2 * h]      = ffma2(a2.x, wr, m[2 * h]);
                m[2 * h + 1]  = ffma2(a2.y, wr, m[2 * h + 1]);
                m[2 * h]      = ffma2(o2.x, wo, m[2 * h]);
                m[2 * h + 1]  = ffma2(o2.y, wo, m[2 * h + 1]);
                sr[2 * h]     = ffma2(o2.x, hr, sr[2 * h]);
                sr[2 * h + 1] = ffma2(o2.y, hr, sr[2 * h + 1]);
                sz[2 * h]     = ffma2(o2.x, hz, sz[2 * h]);
                sz[2 * h + 1] = ffma2(o2.y, hz, sz[2 * h + 1]);
                hn[2 * h]     = ffma2(o2.x, hnw, hn[2 * h]);
                hn[2 * h + 1] = ffma2(o2.y, hnw, hn[2 * h + 1]);
            }
        }
#pragma unroll
        for (int q = 0; q < 8; q++) {
            float2 v = unpack2(m[q]);
            v.x = fmaxf(v.x, 0.f);
            v.y = fmaxf(v.y, 0.f);
            *(float2*)&msw[d * MS_P + 2 * q] = v;
        }
        __syncwarp();

        u64 inn[8];
        {
            u64 bi = splat2(sb_in[d]);
#pragma unroll
            for (int q = 0; q < 8; q++) inn[q] = bi;
        }
#pragma unroll 2
        for (int j = 0; j < 32; j++) {
            u64 ir  = splat2(sWih[j * 32 + d]);
            u64 iz  = splat2(sWih[(32 + j) * 32 + d]);
            u64 in2 = splat2(sWih[(64 + j) * 32 + d]);
#pragma unroll
            for (int h = 0; h < 4; h++) {
                ulonglong2 m2 = *(const ulonglong2*)&msw[j * MS_P + 4 * h];
                sr[2 * h]      = ffma2(m2.x, ir, sr[2 * h]);
                sr[2 * h + 1]  = ffma2(m2.y, ir, sr[2 * h + 1]);
                sz[2 * h]      = ffma2(m2.x, iz, sz[2 * h]);
                sz[2 * h + 1]  = ffma2(m2.y, iz, sz[2 * h + 1]);
                inn[2 * h]     = ffma2(m2.x, in2, inn[2 * h]);
                inn[2 * h + 1] = ffma2(m2.y, in2, inn[2 * h + 1]);
            }
        }

#pragma unroll
        for (int q = 0; q < 8; q++) {
            float2 rs = unpack2(sr[q]);
            float2 zs = unpack2(sz[q]);
            float2 is = unpack2(inn[q]);
            float2 hs = unpack2(hn[q]);
            float2 h  = *(const float2*)&os_[d * AO_P + nl + 2 * q];
            int na = n0 + nl + 2 * q;
            {
                float r = sigm(rs.x), z = sigm(zs.x);
                float nn = tanh_f(fmaf(r, hs.x, is.x));
                if (na < N) g_state[na * DIM + f * ND + d] = fmaf(z, h.x - nn, nn);
            }
            {
                float r = sigm(rs.y), z = sigm(zs.y);
                float nn = tanh_f(fmaf(r, hs.y, is.y));
                if (na + 1 < N) g_state[(na + 1) * DIM + f * ND + d] = fmaf(z, h.y - nn, nn);
            }
        }
    }
}

// ------------------------- K7: segment-mean pooling ------------------------
__global__ __launch_bounds__(128) void k_pool(const int* __restrict__ batch,
                                              float* __restrict__ d_out) {
    int g = blockIdx.x;
    int c = threadIdx.x;
    int lo = 0, hi = N;
    while (lo < hi) { int mid = (lo + hi) >> 1; if (batch[mid] < g) lo = mid + 1; else hi = mid; }
    int s = lo;
    hi = N;
    while (lo < hi) { int mid = (lo + hi) >> 1; if (batch[mid] < g + 1) lo = mid + 1; else hi = mid; }
    int e = lo;
    float sum = 0.f;
    for (int n = s; n < e; n++) sum += g_state[n * DIM + c];
    float cnt = fmaxf((float)(e - s), 1.f);
    float val = __fdividef(sum, cnt);
    g_pooled[g * DIM + c] = val;
    int f = c >> 5, d = c & 31;
    d_out[OFF_OUTS + f * G * ND + g * ND + d] = val;
}

// ------------------------- K8: final MLP -----------------------------------
__global__ __launch_bounds__(128) void k_mlp(const float* __restrict__ fc1_W,
                                             const float* __restrict__ fc1_b,
                                             const float* __restrict__ fc2_W,
                                             const float* __restrict__ fc2_b,
                                             float* __restrict__ d_out) {
    __shared__ float oc[128];
    __shared__ float hid[128];
    int g = blockIdx.x, c = threadIdx.x;
    oc[c] = g_pooled[g * DIM + c];
    __syncthreads();
    float acc = fc1_b[c];
    for (int k = 0; k < DIM; k++) acc = fmaf(oc[k], fc1_W[k * DIM + c], acc);
    hid[c] = fmaxf(acc, 0.f);
    __syncthreads();
    if (c < NC) {
        float p = fc2_b[c];
        for (int k = 0; k < DIM; k++) p = fmaf(hid[k], fc2_W[k * NC + c], p);
        d_out[OFF_PRED + g * NC + c] = p;
    }
}

// ------------------------- launch ------------------------------------------
extern "C" void kernel_launch(void* const* d_in, const int* in_sizes, int n_in,
                              void* d_out_v, int out_size) {
    const float* x          = (const float*)d_in[0];
    const int*   ei         = (const int*)d_in[1];
    const int*   batch      = (const int*)d_in[2];
    const float* lin0_W     = (const float*)d_in[3];
    const float* lin0_b     = (const float*)d_in[4];
    const float* att_W      = (const float*)d_in[5];
    const float* att_b      = (const float*)d_in[6];
    const float* enc_W      = (const float*)d_in[7];
    const float* enc_b      = (const float*)d_in[8];
    const float* conv_Wrel  = (const float*)d_in[9];
    const float* conv_brel  = (const float*)d_in[10];
    const float* conv_Wroot = (const float*)d_in[11];
    const float* gru_Wih    = (const float*)d_in[12];
    const float* gru_Whh    = (const float*)d_in[13];
    const float* gru_bih    = (const float*)d_in[14];
    const float* gru_bhh    = (const float*)d_in[15];
    const float* fc1_W      = (const float*)d_in[16];
    const float* fc1_b      = (const float*)d_in[17];
    const float* fc2_W      = (const float*)d_in[18];
    const float* fc2_b      = (const float*)d_in[19];
    float* out = (float*)d_out_v;

    const int updSmem = (1024 + 1024 + 3072 + 3072 + 64 + 32 + 32 + 32 +
                         2 * 32 * AO_P + 8 * 32 * MS_P) * (int)sizeof(float);  // 87680
    cudaFuncSetAttribute(k_update, cudaFuncAttributeMaxDynamicSharedMemorySize, updSmem);

    // Order keeps k_init as the ncu-profiled launch (index 3).
    k_hist<<<(E + 255) / 256, 256>>>(ei);
    k_scan<<<1, 1024>>>();
    k_pre<<<NF, 128>>>(lin0_W, lin0_b, att_W, att_b);
    k_init<<<(N + I_NPB - 1) / I_NPB, 256>>>(x, enc_W, enc_b);
    k_attscat<<<(E + 255) / 256, 256>>>(ei, out + OFF_ATT);

    const int updGridX = (N + UPD_CHUNKS * 128 - 1) / (UPD_CHUNKS * 128);  // 196
    for (int l = 0; l < NL; l++) {
        k_agg<<<(N * 32 + 255) / 256, 256>>>();
        k_update<<<dim3(updGridX, NF), 256, updSmem>>>(
            conv_Wrel, conv_brel, conv_Wroot,
            gru_Wih, gru_Whh, gru_bih, gru_bhh, l);
    }

    k_pool<<<G, 128>>>(batch, out);
    k_mlp<<<G, 128>>>(fc1_W, fc1_b, fc2_W, fc2_b, out);
}

// round 13
// speedup vs baseline: 1.8068x; 1.0099x over previous
#include <cuda_runtime.h>

#define DINLINE __device__ __forceinline__

constexpr int N   = 50000;
constexpr int E   = 800000;
constexpr int F   = 128;
constexpr int DIM = 128;
constexpr int NF  = 4;
constexpr int ND  = 32;
constexpr int NL  = 3;
constexpr int NC  = 10;
constexpr int G   = 256;

constexpr int OFF_PRED = 0;
constexpr int OFF_ATT  = G * NC;            // 2560
constexpr int OFF_OUTS = OFF_ATT + NF * E;  // 3202560

typedef unsigned long long u64;

// ------------------------- scratch (device globals, no cudaMalloc) ---------
__device__ float  g_state[N * DIM];
__device__ float  g_agg[N * DIM];
__device__ float  g_el[N * NF];
__device__ float  g_er[N * NF];
__device__ float  g_vl[NF * F];
__device__ float  g_vr[NF * F];
__device__ float  g_elb[NF];
__device__ float  g_erb[NF];
__device__ int    g_cnt[N];          // zero at load; k_scan re-zeroes each call
__device__ int    g_rowptr[N + 1];
__device__ int    g_fill[N];
__device__ int    g_csr_src[E];
__device__ float4 g_csr_att[E];
__device__ float  g_pooled[G * DIM];

DINLINE float sigm(float x)   { return __fdividef(1.f, 1.f + __expf(-x)); }
DINLINE float tanh_f(float x) { return 1.f - __fdividef(2.f, __expf(2.f * x) + 1.f); }

// ---- packed f32x2 helpers (FFMA2 — only reachable via PTX) ----------------
DINLINE u64 splat2(float x) { u64 r; asm("mov.b64 %0, {%1, %1};" : "=l"(r) : "f"(x)); return r; }
DINLINE float2 unpack2(u64 v) {
    float lo, hi;
    asm("mov.b64 {%0, %1}, %2;" : "=f"(lo), "=f"(hi) : "l"(v));
    return make_float2(lo, hi);
}
DINLINE u64 ffma2(u64 a, u64 b, u64 c) {
    u64 d;
    asm("fma.rn.f32x2 %0, %1, %2, %3;" : "=l"(d) : "l"(a), "l"(b), "l"(c));
    return d;
}

// ------------------------- K1: fold lin0/att into per-node vectors ---------
__global__ void k_pre(const float* __restrict__ lin0_W, const float* __restrict__ lin0_b,
                      const float* __restrict__ att_W,  const float* __restrict__ att_b) {
    int f = blockIdx.x;
    int k = threadIdx.x;
    const float* W  = lin0_W + (f * F + k) * DIM;
    const float* wl = att_W + f * 2 * DIM;
    const float* wr = wl + DIM;
    float sl = 0.f, sr = 0.f;
    for (int d = 0; d < DIM; d++) { float w = W[d]; sl = fmaf(w, wl[d], sl); sr = fmaf(w, wr[d], sr); }
    g_vl[f * F + k] = sl;
    g_vr[f * F + k] = sr;
    if (k == 0) {
        float bl = att_b[f], br = 0.f;
        const float* b0 = lin0_b + f * DIM;
        for (int d = 0; d < DIM; d++) { bl = fmaf(b0[d], wl[d], bl); br = fmaf(b0[d], wr[d], br); }
        g_elb[f] = bl;
        g_erb[f] = br;
    }
}

// ------------------------- K2: node init (enc GEMM + el/er GEMVs) ----------
// v3: ALL inner-loop operands from SMEM. enc_W staged in two 32KB halves so
// the k-loop is pure LDS (29-cyc, pipelined) + FFMA2 — no L2-latency loads.
// Thread = (4 cols cg*4, 8 nodes ng*8); per k: 1 LDS.128 w + 2 bcast LDS.128 x
// + 4 splats + 16 FFMA2.
constexpr int I_NPB   = 64;
constexpr int I_PITCH = 68;
constexpr int I_SMEM  = (F * I_PITCH + 64 * 128 + 2 * NF * F) * (int)sizeof(float); // 71680
__global__ __launch_bounds__(256) void k_init(const float* __restrict__ x,
                                              const float* __restrict__ enc_W,
                                              const float* __restrict__ enc_b) {
    extern __shared__ __align__(16) float ism[];
    float* xs = ism;                   // [k][n] pitch 68 : 34816 B
    float* ws = xs + F * I_PITCH;      // [kk][c] 64x128  : 32768 B
    float* wv = ws + 64 * 128;         // vl|vr          :  4096 B

    int tid = threadIdx.x;
    int n0  = blockIdx.x * I_NPB;

    for (int i = tid; i < I_NPB * F; i += 256) {
        int n = i >> 7, k = i & 127;
        int node = n0 + n;
        xs[k * I_PITCH + n] = (node < N) ? x[node * F + k] : 0.f;
    }
    for (int i = tid; i < 2 * NF * F; i += 256)
        wv[i] = (i < NF * F) ? g_vl[i] : g_vr[i - NF * F];

    int cg = tid & 31, ng = tid >> 5;
    int c0 = cg * 4;
    int f  = c0 >> 5, d0 = c0 & 31;
    const float* xb = xs + ng * 8;

    u64 acc[4][4];
#pragma unroll
    for (int i = 0; i < 4; i++)
#pragma unroll
        for (int q = 0; q < 4; q++) acc[i][q] = 0ull;

#pragma unroll
    for (int half = 0; half < 2; half++) {
        __syncthreads();   // 1st: xs/wv staged; 2nd: prior compute done before restage
        for (int i = tid; i < 64 * 128; i += 256) {
            int kk = i >> 7, c = i & 127;
            int ff = c >> 5, dd = c & 31;
            ws[i] = enc_W[ff * F * ND + (half * 64 + kk) * ND + dd];
        }
        __syncthreads();

        const float* xh = xb + half * 64 * I_PITCH;
#pragma unroll 4
        for (int kk = 0; kk < 64; kk++) {
            float4 w4 = *(const float4*)&ws[kk * 128 + c0];
            u64 w0 = splat2(w4.x), w1 = splat2(w4.y), w2 = splat2(w4.z), w3 = splat2(w4.w);
            ulonglong2 xA = *(const ulonglong2*)(xh + kk * I_PITCH);
            ulonglong2 xB = *(const ulonglong2*)(xh + kk * I_PITCH + 4);
            acc[0][0] = ffma2(xA.x, w0, acc[0][0]); acc[0][1] = ffma2(xA.y, w0, acc[0][1]);
            acc[0][2] = ffma2(xB.x, w0, acc[0][2]); acc[0][3] = ffma2(xB.y, w0, acc[0][3]);
            acc[1][0] = ffma2(xA.x, w1, acc[1][0]); acc[1][1] = ffma2(xA.y, w1, acc[1][1]);
            acc[1][2] = ffma2(xB.x, w1, acc[1][2]); acc[1][3] = ffma2(xB.y, w1, acc[1][3]);
            acc[2][0] = ffma2(xA.x, w2, acc[2][0]); acc[2][1] = ffma2(xA.y, w2, acc[2][1]);
            acc[2][2] = ffma2(xB.x, w2, acc[2][2]); acc[2][3] = ffma2(xB.y, w2, acc[2][3]);
            acc[3][0] = ffma2(xA.x, w3, acc[3][0]); acc[3][1] = ffma2(xA.y, w3, acc[3][1]);
            acc[3][2] = ffma2(xB.x, w3, acc[3][2]); acc[3][3] = ffma2(xB.y, w3, acc[3][3]);
        }
    }

    float4 b4 = *(const float4*)&enc_b[f * ND + d0];
#pragma unroll
    for (int q = 0; q < 4; q++) {
        float2 v0 = unpack2(acc[0][q]);
        float2 v1 = unpack2(acc[1][q]);
        float2 v2 = unpack2(acc[2][q]);
        float2 v3 = unpack2(acc[3][q]);
        int na = n0 + ng * 8 + 2 * q;
        if (na < N)
            *(float4*)&g_state[na * DIM + c0] =
                make_float4(v0.x + b4.x, v1.x + b4.y, v2.x + b4.z, v3.x + b4.w);
        if (na + 1 < N)
            *(float4*)&g_state[(na + 1) * DIM + c0] =
                make_float4(v0.y + b4.x, v1.y + b4.y, v2.y + b4.z, v3.y + b4.w);
    }

    // el/er: 64 nodes x 8 combos = 512 tasks, 2 per thread (xs/wv still valid)
#pragma unroll
    for (int rep = 0; rep < 2; rep++) {
        int t = tid + rep * 256;
        int n = t >> 3;
        int combo = t & 7;
        int ff = combo & 3, isR = combo >> 2;
        const float* vec = &wv[isR * NF * F + ff * F];
        float a = 0.f;
        for (int k = 0; k < F; k++) a = fmaf(xs[k * I_PITCH + n], vec[k], a);
        int node = n0 + n;
        if (node < N) {
            if (isR) g_er[node * NF + ff] = a + g_erb[ff];
            else     g_el[node * NF + ff] = a + g_elb[ff];
        }
    }
}

// ------------------------- K3: CSR build (hist + scan) ---------------------
__global__ void k_hist(const int* __restrict__ ei) {
    int e = blockIdx.x * blockDim.x + threadIdx.x;
    if (e < E) atomicAdd(&g_cnt[ei[E + e]], 1);
}
__global__ __launch_bounds__(1024) void k_scan() {
    __shared__ int ssum[1024];
    int t = threadIdx.x;
    const int CH = (N + 1023) / 1024;  // 49
    int base = t * CH;
    int s = 0;
    for (int i = 0; i < CH; i++) { int idx = base + i; if (idx < N) s += g_cnt[idx]; }
    ssum[t] = s;
    __syncthreads();
    for (int off = 1; off < 1024; off <<= 1) {
        int v = (t >= off) ? ssum[t - off] : 0;
        __syncthreads();
        ssum[t] += v;
        __syncthreads();
    }
    int run = ssum[t] - s;  // exclusive
    for (int i = 0; i < CH; i++) {
        int idx = base + i;
        if (idx < N) {
            int c = g_cnt[idx];
            g_rowptr[idx] = run;
            g_fill[idx]   = run;
            run += c;
            g_cnt[idx] = 0;   // restore for graph replay
        }
    }
    if (t == 1023) g_rowptr[N] = ssum[1023];
}

// ------------------------- K4: fused attention + CSR scatter ---------------
__global__ void k_attscat(const int* __restrict__ ei, float* __restrict__ out_att) {
    int e = blockIdx.x * blockDim.x + threadIdx.x;
    if (e >= E) return;
    int s = ei[e], d = ei[E + e];
    float4 el = *(const float4*)&g_el[s * 4];
    float4 er = *(const float4*)&g_er[d * 4];
    float4 a;
    a.x = sigm(6.f * (el.x + er.x));
    a.y = sigm(6.f * (el.y + er.y));
    a.z = sigm(6.f * (el.z + er.z));
    a.w = sigm(6.f * (el.w + er.w));
    out_att[0 * E + e] = a.x;
    out_att[1 * E + e] = a.y;
    out_att[2 * E + e] = a.z;
    out_att[3 * E + e] = a.w;
    int pos = atomicAdd(&g_fill[d], 1);
    g_csr_src[pos] = s;
    g_csr_att[pos] = a;
}

// ------------------------- K5: per-layer aggregation (warp per node) -------
// Prefetch depth 2 to cover the src->state pointer chase.
__global__ __launch_bounds__(256) void k_agg() {
    int warp = (blockIdx.x * blockDim.x + threadIdx.x) >> 5;
    int lane = threadIdx.x & 31;
    if (warp >= N) return;
    int beg = g_rowptr[warp], end = g_rowptr[warp + 1];
    const float4* sp = (const float4*)g_state;
    int f = lane >> 3;
    float ax = 0.f, ay = 0.f, az = 0.f, aw = 0.f;
    int    s0 = 0, s1 = 0;
    float4 a0 = make_float4(0.f, 0.f, 0.f, 0.f), a1 = a0;
    if (beg < end)     { s0 = __ldg(&g_csr_src[beg]);     a0 = g_csr_att[beg]; }
    if (beg + 1 < end) { s1 = __ldg(&g_csr_src[beg + 1]); a1 = g_csr_att[beg + 1]; }
    for (int p = beg; p < end; p++) {
        int    s2 = s1;
        float4 a2 = a1;
        if (p + 2 < end) { s2 = __ldg(&g_csr_src[p + 2]); a2 = g_csr_att[p + 2]; }
        float av = (f == 0) ? a0.x : (f == 1) ? a0.y : (f == 2) ? a0.z : a0.w;
        float4 v = sp[s0 * 32 + lane];
        ax = fmaf(av, v.x, ax);
        ay = fmaf(av, v.y, ay);
        az = fmaf(av, v.z, az);
        aw = fmaf(av, v.w, aw);
        s0 = s1; a0 = a1;
        s1 = s2; a1 = a2;
    }
    ((float4*)g_agg)[warp * 32 + lane] = make_float4(ax, ay, az, aw);
}

// ------------------------- K6: fused conv + GRU update ---------------------
// 256 threads = 8 warps; each warp handles 16 nodes (lane d = output dim).
// 2 chunks of 128 nodes per block.
constexpr int UPD_CHUNKS = 2;               // 2 x 128 = 256 nodes per block
constexpr int AO_P  = 132;                  // [j][node] pitch (128 + pad, 16B-aligned)
constexpr int MS_P  = 20;                   // per-warp m staging pitch (16 + pad)
__global__ __launch_bounds__(256) void k_update(
    const float* __restrict__ Wrel, const float* __restrict__ brel,
    const float* __restrict__ Wroot,
    const float* __restrict__ Wih, const float* __restrict__ Whh,
    const float* __restrict__ bih, const float* __restrict__ bhh, int l) {
    extern __shared__ float sm[];
    float* sWrel  = sm;                  // 1024  [j][d]
    float* sWroot = sWrel + 1024;        // 1024  [j][d]
    float* sWih   = sWroot + 1024;       // 3072  [g][j][d]
    float* sWhh   = sWih + 3072;         // 3072  [g][j][d]
    float* sb_rz  = sWhh + 3072;         // 64
    float* sb_in  = sb_rz + 64;          // 32
    float* sb_hn  = sb_in + 32;          // 32
    float* sbrel  = sb_hn + 32;          // 32
    float* as_    = sbrel + 32;          // 4224  [j][node] pitch 132
    float* os_    = as_ + 32 * AO_P;     // 4224
    float* ms_    = os_ + 32 * AO_P;     // 8 warps * 32*20 = 5120

    int f   = blockIdx.y;
    int tid = threadIdx.x;

    const float* Wrel_g  = Wrel + (f * NL + l) * 1024;
    const float* Wroot_g = Wroot + (f * NL + l) * 1024;
    for (int i = tid; i < 1024; i += 256) { sWrel[i] = Wrel_g[i]; sWroot[i] = Wroot_g[i]; }
    const float* Wih_g = Wih + f * 3072;
    const float* Whh_g = Whh + f * 3072;
    for (int i = tid; i < 3072; i += 256) {
        int g = i >> 10, r = (i >> 5) & 31, j = i & 31;
        int t = (g * 32 + j) * 32 + r;   // transposed: [g][j][d]
        sWih[t] = Wih_g[i];
        sWhh[t] = Whh_g[i];
    }
    if (tid < 64) sb_rz[tid] = bih[f * 96 + tid] + bhh[f * 96 + tid];
    if (tid < 32) {
        sb_in[tid] = bih[f * 96 + 64 + tid];
        sb_hn[tid] = bhh[f * 96 + 64 + tid];
        sbrel[tid] = brel[(f * NL + l) * 32 + tid];
    }

    int w = tid >> 5, d = tid & 31, nl = w * 16;
    float* msw = ms_ + w * 32 * MS_P;

    for (int c = 0; c < UPD_CHUNKS; c++) {
        int n0 = (blockIdx.x * UPD_CHUNKS + c) * 128;
        __syncthreads();   // weights ready (1st) / protect as_, os_, ms_ (rest)
        for (int u = tid; u < 4096; u += 256) {
            int j = u & 31, n = u >> 5, node = n0 + n;
            float a = 0.f, o = 0.f;
            if (node < N) {
                a = g_agg[node * DIM + f * ND + j];
                o = g_state[node * DIM + f * ND + j];
            }
            as_[j * AO_P + n] = a;
            os_[j * AO_P + n] = o;
        }
        __syncthreads();

        u64 m[8], sr[8], sz[8], hn[8];
        {
            u64 bm = splat2(sbrel[d]);
            u64 br = splat2(sb_rz[d]);
            u64 bz = splat2(sb_rz[32 + d]);
            u64 bn = splat2(sb_hn[d]);
#pragma unroll
            for (int q = 0; q < 8; q++) { m[q] = bm; sr[q] = br; sz[q] = bz; hn[q] = bn; }
        }
#pragma unroll 2
        for (int j = 0; j < 32; j++) {
            u64 wr  = splat2(sWrel[j * 32 + d]);
            u64 wo  = splat2(sWroot[j * 32 + d]);
            u64 hr  = splat2(sWhh[j * 32 + d]);
            u64 hz  = splat2(sWhh[(32 + j) * 32 + d]);
            u64 hnw = splat2(sWhh[(64 + j) * 32 + d]);
#pragma unroll
            for (int h = 0; h < 4; h++) {
                ulonglong2 a2 = *(const ulonglong2*)&as_[j * AO_P + nl + 4 * h];
                ulonglong2 o2 = *(const ulonglong2*)&os_[j * AO_P + nl + 4 * h];
                m[2 * h]      = ffma2(a2.x, wr, m[2 * h]);
                m[2 * h + 1]  = ffma2(a2.y, wr, m[2 * h + 1]);
                m[2 * h]      = ffma2(o2.x, wo, m[2 * h]);
                m[2 * h + 1]  = ffma2(o2.y, wo, m[2 * h + 1]);
                sr[2 * h]     = ffma2(o2.x, hr, sr[2 * h]);
                sr[2 * h + 1] = ffma2(o2.y, hr, sr[2 * h + 1]);
                sz[2 * h]     = ffma2(o2.x, hz, sz[2 * h]);
                sz[2 * h + 1] = ffma2(o2.y, hz, sz[2 * h + 1]);
                hn[2 * h]     = ffma2(o2.x, hnw, hn[2 * h]);
                hn[2 * h + 1] = ffma2(o2.y, hnw, hn[2 * h + 1]);
            }
        }
#pragma unroll
        for (int q = 0; q < 8; q++) {
            float2 v = unpack2(m[q]);
            v.x = fmaxf(v.x, 0.f);
            v.y = fmaxf(v.y, 0.f);
            *(float2*)&msw[d * MS_P + 2 * q] = v;
        }
        __syncwarp();

        u64 inn[8];
        {
            u64 bi = splat2(sb_in[d]);
#pragma unroll
            for (int q = 0; q < 8; q++) inn[q] = bi;
        }
#pragma unroll 2
        for (int j = 0; j < 32; j++) {
            u64 ir  = splat2(sWih[j * 32 + d]);
            u64 iz  = splat2(sWih[(32 + j) * 32 + d]);
            u64 in2 = splat2(sWih[(64 + j) * 32 + d]);
#pragma unroll
            for (int h = 0; h < 4; h++) {
                ulonglong2 m2 = *(const ulonglong2*)&msw[j * MS_P + 4 * h];
                sr[2 * h]      = ffma2(m2.x, ir, sr[2 * h]);
                sr[2 * h + 1]  = ffma2(m2.y, ir, sr[2 * h + 1]);
                sz[2 * h]      = ffma2(m2.x, iz, sz[2 * h]);
                sz[2 * h + 1]  = ffma2(m2.y, iz, sz[2 * h + 1]);
                inn[2 * h]     = ffma2(m2.x, in2, inn[2 * h]);
                inn[2 * h + 1] = ffma2(m2.y, in2, inn[2 * h + 1]);
            }
        }

#pragma unroll
        for (int q = 0; q < 8; q++) {
            float2 rs = unpack2(sr[q]);
            float2 zs = unpack2(sz[q]);
            float2 is = unpack2(inn[q]);
            float2 hs = unpack2(hn[q]);
            float2 h  = *(const float2*)&os_[d * AO_P + nl + 2 * q];
            int na = n0 + nl + 2 * q;
            {
                float r = sigm(rs.x), z = sigm(zs.x);
                float nn = tanh_f(fmaf(r, hs.x, is.x));
                if (na < N) g_state[na * DIM + f * ND + d] = fmaf(z, h.x - nn, nn);
            }
            {
                float r = sigm(rs.y), z = sigm(zs.y);
                float nn = tanh_f(fmaf(r, hs.y, is.y));
                if (na + 1 < N) g_state[(na + 1) * DIM + f * ND + d] = fmaf(z, h.y - nn, nn);
            }
        }
    }
}

// ------------------------- K7: segment-mean pooling ------------------------
__global__ __launch_bounds__(128) void k_pool(const int* __restrict__ batch,
                                              float* __restrict__ d_out) {
    int g = blockIdx.x;
    int c = threadIdx.x;
    int lo = 0, hi = N;
    while (lo < hi) { int mid = (lo + hi) >> 1; if (batch[mid] < g) lo = mid + 1; else hi = mid; }
    int s = lo;
    hi = N;
    while (lo < hi) { int mid = (lo + hi) >> 1; if (batch[mid] < g + 1) lo = mid + 1; else hi = mid; }
    int e = lo;
    float sum = 0.f;
    for (int n = s; n < e; n++) sum += g_state[n * DIM + c];
    float cnt = fmaxf((float)(e - s), 1.f);
    float val = __fdividef(sum, cnt);
    g_pooled[g * DIM + c] = val;
    int f = c >> 5, d = c & 31;
    d_out[OFF_OUTS + f * G * ND + g * ND + d] = val;
}

// ------------------------- K8: final MLP -----------------------------------
__global__ __launch_bounds__(128) void k_mlp(const float* __restrict__ fc1_W,
                                             const float* __restrict__ fc1_b,
                                             const float* __restrict__ fc2_W,
                                             const float* __restrict__ fc2_b,
                                             float* __restrict__ d_out) {
    __shared__ float oc[128];
    __shared__ float hid[128];
    int g = blockIdx.x, c = threadIdx.x;
    oc[c] = g_pooled[g * DIM + c];
    __syncthreads();
    float acc = fc1_b[c];
    for (int k = 0; k < DIM; k++) acc = fmaf(oc[k], fc1_W[k * DIM + c], acc);
    hid[c] = fmaxf(acc, 0.f);
    __syncthreads();
    if (c < NC) {
        float p = fc2_b[c];
        for (int k = 0; k < DIM; k++) p = fmaf(hid[k], fc2_W[k * NC + c], p);
        d_out[OFF_PRED + g * NC + c] = p;
    }
}

// ------------------------- launch ------------------------------------------
extern "C" void kernel_launch(void* const* d_in, const int* in_sizes, int n_in,
                              void* d_out_v, int out_size) {
    const float* x          = (const float*)d_in[0];
    const int*   ei         = (const int*)d_in[1];
    const int*   batch      = (const int*)d_in[2];
    const float* lin0_W     = (const float*)d_in[3];
    const float* lin0_b     = (const float*)d_in[4];
    const float* att_W      = (const float*)d_in[5];
    const float* att_b      = (const float*)d_in[6];
    const float* enc_W      = (const float*)d_in[7];
    const float* enc_b      = (const float*)d_in[8];
    const float* conv_Wrel  = (const float*)d_in[9];
    const float* conv_brel  = (const float*)d_in[10];
    const float* conv_Wroot = (const float*)d_in[11];
    const float* gru_Wih    = (const float*)d_in[12];
    const float* gru_Whh    = (const float*)d_in[13];
    const float* gru_bih    = (const float*)d_in[14];
    const float* gru_bhh    = (const float*)d_in[15];
    const float* fc1_W      = (const float*)d_in[16];
    const float* fc1_b      = (const float*)d_in[17];
    const float* fc2_W      = (const float*)d_in[18];
    const float* fc2_b      = (const float*)d_in[19];
    float* out = (float*)d_out_v;

    cudaFuncSetAttribute(k_init, cudaFuncAttributeMaxDynamicSharedMemorySize, I_SMEM);
    const int updSmem = (1024 + 1024 + 3072 + 3072 + 64 + 32 + 32 + 32 +
                         2 * 32 * AO_P + 8 * 32 * MS_P) * (int)sizeof(float);  // 87680
    cudaFuncSetAttribute(k_update, cudaFuncAttributeMaxDynamicSharedMemorySize, updSmem);

    k_hist<<<(E + 255) / 256, 256>>>(ei);
    k_scan<<<1, 1024>>>();
    k_pre<<<NF, 128>>>(lin0_W, lin0_b, att_W, att_b);

    // PROFILED SLOT (launch index 3): quarter-grid dummy k_update.
    // Reads stale g_agg/g_state (deterministic per replay); its g_state writes
    // are fully overwritten by k_init below, so output is unaffected. Purpose:
    // obtain ncu pipe/occupancy/issue stats for the real update kernel.
    k_update<<<dim3(49, NF), 256, updSmem>>>(conv_Wrel, conv_brel, conv_Wroot,
                                             gru_Wih, gru_Whh, gru_bih, gru_bhh, 0);

    k_init<<<(N + I_NPB - 1) / I_NPB, 256, I_SMEM>>>(x, enc_W, enc_b);
    k_attscat<<<(E + 255) / 256, 256>>>(ei, out + OFF_ATT);

    const int updGridX = (N + UPD_CHUNKS * 128 - 1) / (UPD_CHUNKS * 128);  // 196
    for (int l = 0; l < NL; l++) {
        k_agg<<<(N * 32 + 255) / 256, 256>>>();
        k_update<<<dim3(updGridX, NF), 256, updSmem>>>(
            conv_Wrel, conv_brel, conv_Wroot,
            gru_Wih, gru_Whh, gru_bih, gru_bhh, l);
    }

    k_pool<<<G, 128>>>(batch, out);
    k_mlp<<<G, 128>>>(fc1_W, fc1_b, fc2_W, fc2_b, out);
}